// round 6
// baseline (speedup 1.0000x reference)
#include <cuda_runtime.h>
#include <cuda_fp16.h>
#include <cuda_bf16.h>
#include <math.h>

#define NA 50000
#define NP 100000
#define DA 512
#define DP 256
#define HID 64
#define NOUT 16
#define NE 2000000
#define CH 2048
#define NCH_A 25   // ceil(50000/2048)
#define NCH_P 49   // ceil(100000/2048)
#define NBLK_SCAN (NCH_A + 2*NCH_P)   // 123
#define BA_BLOCKS 3125   // NA/2 nodes -> 25000 warps
#define BP_BLOCKS 6250
#define GEMM_A_BLOCKS 391  // ceil(50000/128)
#define GEMM_P_BLOCKS 782  // ceil(100000/128)
#define XS_STRIDE 132      // multiple of 4 so every row is 16B-aligned for LDS.128

// ---------------- scratch ----------------
__device__ float g_xa[NA * HID];
__device__ float g_xp[NP * HID];
__device__ float g_ha[NA * HID];          // fp32 final-hop A output only (fc2 input)
// fp16 gather mirrors; buffer index 2 == x mirror
__device__ __align__(16) __half2 g_h16a[3 * NA * 32];
__device__ __align__(16) __half2 g_h16p[3 * NP * 32];

__device__ int g_rp_ap[NA + 1];
__device__ int g_rp_pa[NP + 1];
__device__ int g_rp_pp[NP + 1];
__device__ int g_ts_ap[NE];
__device__ int g_ts_pa[NE];
__device__ int g_ts_pp[NE];
__device__ int g_cntA[NA];
__device__ int g_cntP1[NP];
__device__ int g_cntP2[NP];
__device__ int g_bsum[3 * 64];

// x-based attention scalars, all hops precomputed
__device__ float g_x1ap[3 * NA], g_x2ap[3 * NA];
__device__ float g_x1pa[3 * NP], g_x2pa[3 * NP], g_x1pp[3 * NP], g_x2pp[3 * NP];
// h-based scalars, double buffered
__device__ float g_h1pa[2 * NA];
__device__ float g_h1ap[2 * NP], g_h1pp[2 * NP];

// ---------------- helpers ----------------
__device__ __forceinline__ const __half2* bufA16(int c) { return g_h16a + (size_t)c * NA * 32; }
__device__ __forceinline__ const __half2* bufP16(int c) { return g_h16p + (size_t)c * NP * 32; }
__device__ __forceinline__ float eluf(float v) { return v > 0.f ? v : expm1f(v); }
__device__ __forceinline__ float lrelu_exp(float sc) {
    sc = sc >= 0.f ? sc : 0.2f * sc;
    return __expf(sc);
}
__device__ __forceinline__ float wred32(float v) {
    v += __shfl_down_sync(0xffffffffu, v, 16);
    v += __shfl_down_sync(0xffffffffu, v, 8);
    v += __shfl_down_sync(0xffffffffu, v, 4);
    v += __shfl_down_sync(0xffffffffu, v, 2);
    v += __shfl_down_sync(0xffffffffu, v, 1);
    return v;
}
__device__ __forceinline__ float wred16(float v) {
    v += __shfl_down_sync(0xffffffffu, v, 8, 16);
    v += __shfl_down_sync(0xffffffffu, v, 4, 16);
    v += __shfl_down_sync(0xffffffffu, v, 2, 16);
    v += __shfl_down_sync(0xffffffffu, v, 1, 16);
    return v;
}
__device__ __forceinline__ unsigned long long pk2(float lo, float hi) {
    unsigned long long r;
    asm("mov.b64 %0, {%1, %2};" : "=l"(r) : "f"(lo), "f"(hi));
    return r;
}
__device__ __forceinline__ void up2(unsigned long long v, float& lo, float& hi) {
    asm("mov.b64 {%0, %1}, %2;" : "=f"(lo), "=f"(hi) : "l"(v));
}
__device__ __forceinline__ void ffma2(unsigned long long& d, unsigned long long a, unsigned long long b) {
    asm("fma.rn.f32x2 %0, %1, %2, %0;" : "+l"(d) : "l"(a), "l"(b));
}
__device__ __forceinline__ uint2 pack_h4(float x, float y, float z, float w) {
    __half2 q0 = __floats2half2_rn(x, y);
    __half2 q1 = __floats2half2_rn(z, w);
    uint2 st;
    st.x = *reinterpret_cast<unsigned*>(&q0);
    st.y = *reinterpret_cast<unsigned*>(&q1);
    return st;
}

// ---------------- CSR build ----------------
__global__ void zero_cnt_kernel() {
    int i = blockIdx.x * blockDim.x + threadIdx.x;
    int stride = gridDim.x * blockDim.x;
    for (; i < NA + 2 * NP; i += stride) {
        if (i < NA) g_cntA[i] = 0;
        else if (i < NA + NP) g_cntP1[i - NA] = 0;
        else g_cntP2[i - NA - NP] = 0;
    }
}

__global__ void hist_kernel(const int* __restrict__ ap_s,
                            const int* __restrict__ pa_s,
                            const int* __restrict__ pp_s) {
    const int Q = NE / 4;   // int4 chunks per relation
    int i = blockIdx.x * blockDim.x + threadIdx.x;
    int stride = gridDim.x * blockDim.x;
    for (; i < 3 * Q; i += stride) {
        int4 v;
        int* cnt;
        if (i < Q)          { v = ((const int4*)ap_s)[i];        cnt = g_cntA;  }
        else if (i < 2 * Q) { v = ((const int4*)pa_s)[i - Q];    cnt = g_cntP1; }
        else                { v = ((const int4*)pp_s)[i - 2 * Q]; cnt = g_cntP2; }
        atomicAdd(&cnt[v.x], 1);
        atomicAdd(&cnt[v.y], 1);
        atomicAdd(&cnt[v.z], 1);
        atomicAdd(&cnt[v.w], 1);
    }
}

__device__ __forceinline__ void rel_of(int b, int& rel, int& chunk) {
    if (b < NCH_A)              { rel = 0; chunk = b; }
    else if (b < NCH_A + NCH_P) { rel = 1; chunk = b - NCH_A; }
    else                        { rel = 2; chunk = b - NCH_A - NCH_P; }
}

__global__ void scan_passA() {
    int rel, chunk; rel_of(blockIdx.x, rel, chunk);
    const int* cnt = rel == 0 ? g_cntA : (rel == 1 ? g_cntP1 : g_cntP2);
    int n = rel == 0 ? NA : NP;
    int base = chunk * CH;
    int s = 0;
    #pragma unroll
    for (int j = 0; j < 8; j++) {
        int i = base + threadIdx.x + 256 * j;
        if (i < n) s += cnt[i];
    }
    #pragma unroll
    for (int o = 16; o; o >>= 1) s += __shfl_down_sync(0xffffffffu, s, o);
    __shared__ int sh[8];
    int lane = threadIdx.x & 31, wid = threadIdx.x >> 5;
    if (lane == 0) sh[wid] = s;
    __syncthreads();
    if (wid == 0) {
        int t = (lane < 8) ? sh[lane] : 0;
        #pragma unroll
        for (int o = 4; o; o >>= 1) t += __shfl_down_sync(0xffffffffu, t, o);
        if (lane == 0) g_bsum[rel * 64 + chunk] = t;
    }
}

__global__ void scan_passB() {   // 1 block, 96 threads
    int wid = threadIdx.x >> 5, lane = threadIdx.x & 31;
    if (wid < 3) {
        int nch = (wid == 0) ? NCH_A : NCH_P;
        int carry = 0;
        #pragma unroll
        for (int c0 = 0; c0 < 64; c0 += 32) {
            int idx = c0 + lane;
            int v = (idx < nch) ? g_bsum[wid * 64 + idx] : 0;
            int x = v;
            #pragma unroll
            for (int o = 1; o < 32; o <<= 1) {
                int y = __shfl_up_sync(0xffffffffu, x, o);
                if (lane >= o) x += y;
            }
            g_bsum[wid * 64 + idx] = carry + x - v;   // exclusive
            carry += __shfl_sync(0xffffffffu, x, 31);
        }
        if (lane == 0) {
            if (wid == 0)      g_rp_ap[NA] = carry;
            else if (wid == 1) g_rp_pa[NP] = carry;
            else               g_rp_pp[NP] = carry;
        }
    }
}

__global__ void scan_passC() {   // re-scan chunk, write rp, zero cnt
    int rel, chunk; rel_of(blockIdx.x, rel, chunk);
    int* cnt; int* rp; int n;
    if (rel == 0)      { cnt = g_cntA;  rp = g_rp_ap; n = NA; }
    else if (rel == 1) { cnt = g_cntP1; rp = g_rp_pa; n = NP; }
    else               { cnt = g_cntP2; rp = g_rp_pp; n = NP; }
    int tid = threadIdx.x, lane = tid & 31, wid = tid >> 5;
    int i0 = chunk * CH + tid * 8;
    int v[8];
    #pragma unroll
    for (int j = 0; j < 8; j++) v[j] = (i0 + j < n) ? cnt[i0 + j] : 0;
    int s = 0;
    #pragma unroll
    for (int j = 0; j < 8; j++) { int t = v[j]; v[j] = s; s += t; }   // local exclusive, s=sum
    int x = s;
    #pragma unroll
    for (int o = 1; o < 32; o <<= 1) {
        int y = __shfl_up_sync(0xffffffffu, x, o);
        if (lane >= o) x += y;
    }
    __shared__ int wsum[8];
    if (lane == 31) wsum[wid] = x;
    __syncthreads();
    if (wid == 0 && lane < 8) {
        int t = wsum[lane];
        int xx = t;
        #pragma unroll
        for (int o = 1; o < 8; o <<= 1) {
            int y = __shfl_up_sync(0xffu, xx, o);
            if (lane >= o) xx += y;
        }
        wsum[lane] = xx - t;   // exclusive warp offsets
    }
    __syncthreads();
    int off = g_bsum[rel * 64 + chunk] + wsum[wid] + (x - s);
    #pragma unroll
    for (int j = 0; j < 8; j++) {
        int i = i0 + j;
        if (i < n) { rp[i] = off + v[j]; cnt[i] = 0; }
    }
}

__global__ void scatter_kernel(const int* __restrict__ ap_s, const int* __restrict__ ap_t,
                               const int* __restrict__ pa_s, const int* __restrict__ pa_t,
                               const int* __restrict__ pp_s, const int* __restrict__ pp_t) {
    int i = blockIdx.x * blockDim.x + threadIdx.x;
    int stride = gridDim.x * blockDim.x;
    for (; i < 3 * NE; i += stride) {
        if (i < NE) {
            int s = ap_s[i];
            int pos = g_rp_ap[s] + atomicAdd(&g_cntA[s], 1);
            g_ts_ap[pos] = ap_t[i];
        } else if (i < 2 * NE) {
            int e = i - NE;
            int s = pa_s[e];
            int pos = g_rp_pa[s] + atomicAdd(&g_cntP1[s], 1);
            g_ts_pa[pos] = pa_t[e];
        } else {
            int e = i - 2 * NE;
            int s = pp_s[e];
            int pos = g_rp_pp[s] + atomicAdd(&g_cntP2[s], 1);
            g_ts_pp[pos] = pp_t[e];
        }
    }
}

// ---------------- projection GEMM, 128 threads, 128x64 tile, 8x8/thread, FFMA2 ----
__global__ __launch_bounds__(128) void proj_gemm2(
    const float* __restrict__ XA, const float* __restrict__ WA, const float* __restrict__ bA,
    const float* __restrict__ XP, const float* __restrict__ WP, const float* __restrict__ bP) {
    __shared__ __align__(16) float xs[32 * XS_STRIDE];
    __shared__ __align__(16) float ws[32 * 64];
    int b = blockIdx.x;
    const float* X; const float* W; const float* bias; float* Y; __half2* Y16; int N, K, nb;
    if (b < GEMM_A_BLOCKS) {
        X = XA; W = WA; bias = bA; Y = g_xa; N = NA; K = DA; nb = b * 128;
        Y16 = g_h16a + (size_t)2 * NA * 32;
    } else {
        b -= GEMM_A_BLOCKS;
        X = XP; W = WP; bias = bP; Y = g_xp; N = NP; K = DP; nb = b * 128;
        Y16 = g_h16p + (size_t)2 * NP * 32;
    }

    int tid = threadIdx.x;
    int tn = tid & 7, tm = tid >> 3;

    unsigned long long acc[8][4];
    #pragma unroll
    for (int r = 0; r < 8; r++)
        #pragma unroll
        for (int p = 0; p < 4; p++) acc[r][p] = 0ull;

    for (int kc = 0; kc < K; kc += 32) {
        #pragma unroll
        for (int j = 0; j < 8; j++) {
            int idx = tid + 128 * j;
            int node = idx >> 3, kq = idx & 7;
            int gn = nb + node;
            float4 v = (gn < N) ? *(const float4*)&X[(size_t)gn * K + kc + kq * 4]
                                : make_float4(0.f, 0.f, 0.f, 0.f);
            int kb = kq * 4;
            xs[(kb + 0) * XS_STRIDE + node] = v.x;
            xs[(kb + 1) * XS_STRIDE + node] = v.y;
            xs[(kb + 2) * XS_STRIDE + node] = v.z;
            xs[(kb + 3) * XS_STRIDE + node] = v.w;
        }
        #pragma unroll
        for (int j = 0; j < 4; j++) {
            int idx = tid + 128 * j;
            int row = idx >> 4, cq = idx & 15;
            *(float4*)&ws[row * 64 + cq * 4] = *(const float4*)&W[(size_t)(kc + row) * 64 + cq * 4];
        }
        __syncthreads();
        #pragma unroll
        for (int kk = 0; kk < 32; kk++) {
            float4 xv0 = *(const float4*)&xs[kk * XS_STRIDE + tm * 4];
            float4 xv1 = *(const float4*)&xs[kk * XS_STRIDE + 64 + tm * 4];
            float4 wv0 = *(const float4*)&ws[kk * 64 + tn * 4];
            float4 wv1 = *(const float4*)&ws[kk * 64 + 32 + tn * 4];
            unsigned long long wp0 = pk2(wv0.x, wv0.y);
            unsigned long long wp1 = pk2(wv0.z, wv0.w);
            unsigned long long wp2 = pk2(wv1.x, wv1.y);
            unsigned long long wp3 = pk2(wv1.z, wv1.w);
            float xr[8] = {xv0.x, xv0.y, xv0.z, xv0.w, xv1.x, xv1.y, xv1.z, xv1.w};
            #pragma unroll
            for (int r = 0; r < 8; r++) {
                unsigned long long xd = pk2(xr[r], xr[r]);
                ffma2(acc[r][0], xd, wp0);
                ffma2(acc[r][1], xd, wp1);
                ffma2(acc[r][2], xd, wp2);
                ffma2(acc[r][3], xd, wp3);
            }
        }
        __syncthreads();
    }

    float4 bv0 = *(const float4*)&bias[tn * 4];
    float4 bv1 = *(const float4*)&bias[32 + tn * 4];
    #pragma unroll
    for (int r = 0; r < 8; r++) {
        int node = nb + ((r < 4) ? (tm * 4 + r) : (64 + tm * 4 + r - 4));
        if (node < N) {
            float f0, f1, f2, f3, f4, f5, f6, f7;
            up2(acc[r][0], f0, f1);
            up2(acc[r][1], f2, f3);
            up2(acc[r][2], f4, f5);
            up2(acc[r][3], f6, f7);
            float4 o0, o1;
            o0.x = fmaxf(f0 + bv0.x, 0.f); o0.y = fmaxf(f1 + bv0.y, 0.f);
            o0.z = fmaxf(f2 + bv0.z, 0.f); o0.w = fmaxf(f3 + bv0.w, 0.f);
            o1.x = fmaxf(f4 + bv1.x, 0.f); o1.y = fmaxf(f5 + bv1.y, 0.f);
            o1.z = fmaxf(f6 + bv1.z, 0.f); o1.w = fmaxf(f7 + bv1.w, 0.f);
            *(float4*)&Y[(size_t)node * 64 + tn * 4] = o0;
            *(float4*)&Y[(size_t)node * 64 + 32 + tn * 4] = o1;
            // fp16 mirror (x is hop-0 h)
            uint2 m0 = pack_h4(o0.x, o0.y, o0.z, o0.w);
            uint2 m1 = pack_h4(o1.x, o1.y, o1.z, o1.w);
            *reinterpret_cast<uint2*>(&Y16[(size_t)node * 32 + tn * 2]) = m0;
            *reinterpret_cast<uint2*>(&Y16[(size_t)node * 32 + 16 + tn * 2]) = m1;
        }
    }
}

// ---------------- upfront scalar projections (all hops, x-based + hop-0 h-based) ----
__global__ void sproj0_kernel(const float* __restrict__ a1ap, const float* __restrict__ a2ap,
                              const float* __restrict__ a1pa, const float* __restrict__ a2pa,
                              const float* __restrict__ a1pp, const float* __restrict__ a2pp) {
    int gw = (blockIdx.x * blockDim.x + threadIdx.x) >> 5;
    int lane = threadIdx.x & 31;
    if (gw < NA) {
        int n = gw;
        float x0 = g_xa[(size_t)n * 64 + lane], x1 = g_xa[(size_t)n * 64 + 32 + lane];
        #pragma unroll
        for (int h = 0; h < 3; h++) {
            float d1 = wred32(fmaf(x0, a1ap[h * 64 + lane], x1 * a1ap[h * 64 + 32 + lane]));
            float d2 = wred32(fmaf(x0, a2ap[h * 64 + lane], x1 * a2ap[h * 64 + 32 + lane]));
            if (lane == 0) { g_x1ap[h * NA + n] = d1; g_x2ap[h * NA + n] = d2; }
        }
        float d3 = wred32(fmaf(x0, a2pa[lane], x1 * a2pa[32 + lane]));
        if (lane == 0) g_h1pa[n] = d3;   // buffer 0
    } else {
        int n = gw - NA;
        float x0 = g_xp[(size_t)n * 64 + lane], x1 = g_xp[(size_t)n * 64 + 32 + lane];
        #pragma unroll
        for (int h = 0; h < 3; h++) {
            float d1 = wred32(fmaf(x0, a1pa[h * 64 + lane], x1 * a1pa[h * 64 + 32 + lane]));
            float d2 = wred32(fmaf(x0, a2pa[h * 64 + lane], x1 * a2pa[h * 64 + 32 + lane]));
            float d3 = wred32(fmaf(x0, a1pp[h * 64 + lane], x1 * a1pp[h * 64 + 32 + lane]));
            float d4 = wred32(fmaf(x0, a2pp[h * 64 + lane], x1 * a2pp[h * 64 + 32 + lane]));
            if (lane == 0) {
                g_x1pa[h * NP + n] = d1; g_x2pa[h * NP + n] = d2;
                g_x1pp[h * NP + n] = d3; g_x2pp[h * NP + n] = d4;
            }
        }
        float d5 = wred32(fmaf(x0, a2ap[lane], x1 * a2ap[32 + lane]));
        float d6 = wred32(fmaf(x0, a2pp[lane], x1 * a2pp[32 + lane]));
        if (lane == 0) { g_h1ap[n] = d5; g_h1pp[n] = d6; }   // buffer 0
    }
}

// ---------------- merged edge aggregation (fp16 gathers, fp32 math) ----------------
__device__ __forceinline__ void relation_accum16(const int* __restrict__ rp,
                                                 const int* __restrict__ ts,
                                                 const __half2* __restrict__ h16,
                                                 const float* __restrict__ h1arr,
                                                 float x1, int n, int sub,
                                                 float4& acc, float& div) {
    int e = rp[n], end = rp[n + 1];
    #pragma unroll 4
    for (; e < end; ++e) {
        int t = __ldg(&ts[e]);
        float w = lrelu_exp(x1 + __ldg(&h1arr[t]));
        uint2 rv = *reinterpret_cast<const uint2*>(&h16[(size_t)t * 32 + (sub << 1)]);
        __half2 a = *reinterpret_cast<const __half2*>(&rv.x);
        __half2 bb = *reinterpret_cast<const __half2*>(&rv.y);
        float2 f0 = __half22float2(a);
        float2 f1 = __half22float2(bb);
        acc.x = fmaf(w, f0.x, acc.x);
        acc.y = fmaf(w, f0.y, acc.y);
        acc.z = fmaf(w, f1.x, acc.z);
        acc.w = fmaf(w, f1.y, acc.w);
        div += w;
    }
}

__global__ void agg_kernel(int curA, int curP, int nxt, int h1cur, int h1nxt, int hop, int last,
                           const float* __restrict__ a2pa_nx,
                           const float* __restrict__ a2ap_nx,
                           const float* __restrict__ a2pp_nx) {
    int lane = threadIdx.x & 31;
    int sub = lane & 15;
    int half = lane >> 4;
    if (blockIdx.x < BA_BLOCKS) {
        int warp = (blockIdx.x * blockDim.x + threadIdx.x) >> 5;
        int n = warp * 2 + half;            // exact cover of NA
        const __half2* __restrict__ h = bufP16(curP);
        const float* __restrict__ h1 = g_h1ap + (size_t)h1cur * NP;
        float x1 = g_x1ap[hop * NA + n];
        float4 acc = {0.f, 0.f, 0.f, 0.f};
        float div = 0.f;
        relation_accum16(g_rp_ap, g_ts_ap, h, h1, x1, n, sub, acc, div);
        float w2 = lrelu_exp(x1 + g_x2ap[hop * NA + n]);
        const float4 xv = *reinterpret_cast<const float4*>(&g_xa[(size_t)n * 64 + (sub << 2)]);
        acc.x = fmaf(w2, xv.x, acc.x); acc.y = fmaf(w2, xv.y, acc.y);
        acc.z = fmaf(w2, xv.z, acc.z); acc.w = fmaf(w2, xv.w, acc.w);
        div += w2;
        float inv = 1.f / div;
        float4 r;
        r.x = eluf(acc.x * inv); r.y = eluf(acc.y * inv);
        r.z = eluf(acc.z * inv); r.w = eluf(acc.w * inv);
        if (last) {
            // fp32 output for fc2
            *reinterpret_cast<float4*>(&g_ha[(size_t)n * 64 + (sub << 2)]) = r;
        } else {
            uint2 st = pack_h4(r.x, r.y, r.z, r.w);
            *reinterpret_cast<uint2*>(&g_h16a[((size_t)nxt * NA + n) * 32 + (sub << 1)]) = st;
            const float4 va = *(const float4*)&a2pa_nx[sub << 2];
            float p = r.x * va.x + r.y * va.y + r.z * va.z + r.w * va.w;
            p = wred16(p);
            if (sub == 0) g_h1pa[(size_t)h1nxt * NA + n] = p;
        }
    } else {
        int warp = ((blockIdx.x - BA_BLOCKS) * blockDim.x + threadIdx.x) >> 5;
        int n = warp * 2 + half;            // exact cover of NP
        const __half2* __restrict__ hA = bufA16(curA);
        const __half2* __restrict__ hP = bufP16(curP);
        const float* __restrict__ h1a = g_h1pa + (size_t)h1cur * NA;
        const float* __restrict__ h1p = g_h1pp + (size_t)h1cur * NP;
        float x1a = g_x1pa[hop * NP + n];
        float x1p = g_x1pp[hop * NP + n];
        float4 acc1 = {0.f, 0.f, 0.f, 0.f}, acc2 = {0.f, 0.f, 0.f, 0.f};
        float div1 = 0.f, div2 = 0.f;
        relation_accum16(g_rp_pa, g_ts_pa, hA, h1a, x1a, n, sub, acc1, div1);
        relation_accum16(g_rp_pp, g_ts_pp, hP, h1p, x1p, n, sub, acc2, div2);
        const float4 xv = *reinterpret_cast<const float4*>(&g_xp[(size_t)n * 64 + (sub << 2)]);
        float w2a = lrelu_exp(x1a + g_x2pa[hop * NP + n]);
        float w2p = lrelu_exp(x1p + g_x2pp[hop * NP + n]);
        acc1.x = fmaf(w2a, xv.x, acc1.x); acc1.y = fmaf(w2a, xv.y, acc1.y);
        acc1.z = fmaf(w2a, xv.z, acc1.z); acc1.w = fmaf(w2a, xv.w, acc1.w);
        div1 += w2a;
        acc2.x = fmaf(w2p, xv.x, acc2.x); acc2.y = fmaf(w2p, xv.y, acc2.y);
        acc2.z = fmaf(w2p, xv.z, acc2.z); acc2.w = fmaf(w2p, xv.w, acc2.w);
        div2 += w2p;
        float i1 = 1.f / div1, i2 = 1.f / div2;
        float4 r;
        r.x = eluf(0.5f * (acc1.x * i1 + acc2.x * i2));
        r.y = eluf(0.5f * (acc1.y * i1 + acc2.y * i2));
        r.z = eluf(0.5f * (acc1.z * i1 + acc2.z * i2));
        r.w = eluf(0.5f * (acc1.w * i1 + acc2.w * i2));
        if (!last) {
            uint2 st = pack_h4(r.x, r.y, r.z, r.w);
            *reinterpret_cast<uint2*>(&g_h16p[((size_t)nxt * NP + n) * 32 + (sub << 1)]) = st;
            const float4 va = *(const float4*)&a2ap_nx[sub << 2];
            const float4 vp = *(const float4*)&a2pp_nx[sub << 2];
            float p1 = r.x * va.x + r.y * va.y + r.z * va.z + r.w * va.w;
            float p2 = r.x * vp.x + r.y * vp.y + r.z * vp.z + r.w * vp.w;
            p1 = wred16(p1);
            p2 = wred16(p2);
            if (sub == 0) {
                g_h1ap[(size_t)h1nxt * NP + n] = p1;
                g_h1pp[(size_t)h1nxt * NP + n] = p2;
            }
        }
    }
}

// ---------------- final projection ----------------
__global__ void final_fc2_kernel(const float* __restrict__ W,
                                 const float* __restrict__ b,
                                 float* __restrict__ out) {
    __shared__ float ws[64 * 16];
    int tid = threadIdx.x;
    for (int i = tid; i < 64 * 16; i += blockDim.x) ws[i] = W[i];
    __syncthreads();
    const float* h = g_ha;
    int j = tid & 15, nl = tid >> 4;
    for (int n = blockIdx.x * 16 + nl; n < NA; n += gridDim.x * 16) {
        float acc = b[j];
        #pragma unroll 8
        for (int k = 0; k < 64; k++) acc = fmaf(h[(size_t)n * 64 + k], ws[k * 16 + j], acc);
        out[(size_t)n * 16 + j] = acc;
    }
}

// ---------------- launch ----------------
extern "C" void kernel_launch(void* const* d_in, const int* in_sizes, int n_in,
                              void* d_out, int out_size) {
    const float* x_a   = (const float*)d_in[0];
    const float* x_p   = (const float*)d_in[1];
    const int* ap_s    = (const int*)d_in[2];
    const int* ap_t    = (const int*)d_in[3];
    const int* pa_s    = (const int*)d_in[4];
    const int* pa_t    = (const int*)d_in[5];
    const int* pp_s    = (const int*)d_in[6];
    const int* pp_t    = (const int*)d_in[7];
    const float* fc1aw = (const float*)d_in[8];
    const float* fc1ab = (const float*)d_in[9];
    const float* fc1pw = (const float*)d_in[10];
    const float* fc1pb = (const float*)d_in[11];
    const float* fc2w  = (const float*)d_in[12];
    const float* fc2b  = (const float*)d_in[13];
    const float* a1ap  = (const float*)d_in[14];
    const float* a2ap  = (const float*)d_in[15];
    const float* a1pa  = (const float*)d_in[16];
    const float* a2pa  = (const float*)d_in[17];
    const float* a1pp  = (const float*)d_in[18];
    const float* a2pp  = (const float*)d_in[19];
    float* out = (float*)d_out;

    // CSR build
    zero_cnt_kernel<<<977, 256>>>();
    hist_kernel<<<1024, 256>>>(ap_s, pa_s, pp_s);
    scan_passA<<<NBLK_SCAN, 256>>>();
    scan_passB<<<1, 96>>>();
    scan_passC<<<NBLK_SCAN, 256>>>();   // also zeroes cnt
    scatter_kernel<<<6000, 256>>>(ap_s, ap_t, pa_s, pa_t, pp_s, pp_t);

    // input projections (merged A+P), writes fp32 + fp16 mirror (index 2)
    proj_gemm2<<<GEMM_A_BLOCKS + GEMM_P_BLOCKS, 128>>>(x_a, fc1aw, fc1ab, x_p, fc1pw, fc1pb);

    // all-hop x-based scalars + hop-0 h-based scalars
    sproj0_kernel<<<(NA + NP) / 8, 256>>>(a1ap, a2ap, a1pa, a2pa, a1pp, a2pp);

    // hops
    int curA = 2, curP = 2, nxt = 0, h1cur = 0, h1nxt = 1;
    for (int hop = 0; hop < 3; hop++) {
        int last = (hop == 2);
        int nh = last ? 2 : (hop + 1);   // next-hop a2 vectors (unused when last)
        agg_kernel<<<BA_BLOCKS + BP_BLOCKS, 256>>>(curA, curP, nxt, h1cur, h1nxt, hop, last,
                                                   a2pa + 64 * nh, a2ap + 64 * nh, a2pp + 64 * nh);
        curA = nxt; curP = nxt;
        nxt ^= 1;
        int t = h1cur; h1cur = h1nxt; h1nxt = t;
    }

    final_fc2_kernel<<<3125, 256>>>(fc2w, fc2b, out);
}

// round 8
// speedup vs baseline: 1.0270x; 1.0270x over previous
#include <cuda_runtime.h>
#include <cuda_fp16.h>
#include <cuda_bf16.h>
#include <math.h>

#define NA 50000
#define NP 100000
#define DA 512
#define DP 256
#define HID 64
#define NOUT 16
#define NE 2000000
#define CH 2048
#define NCH_A 25   // ceil(50000/2048)
#define NCH_P 49   // ceil(100000/2048)
#define NBLK_SCAN (NCH_A + 2*NCH_P)   // 123
#define BA_BLOCKS 3125   // NA/2 nodes -> 25000 warps
#define BP_BLOCKS 6250
#define GEMM_A_BLOCKS 391  // ceil(50000/128)
#define GEMM_P_BLOCKS 782  // ceil(100000/128)
#define XS_STRIDE 132      // multiple of 4 so every row is 16B-aligned for LDS.128

// ---------------- scratch ----------------
__device__ float g_xa[NA * HID];
__device__ float g_xp[NP * HID];
__device__ float g_ha[NA * HID];          // fp32 final-hop A output only (fc2 input)
// fp16 gather mirrors; buffer index 2 == x mirror
__device__ __align__(16) __half2 g_h16a[3 * NA * 32];
__device__ __align__(16) __half2 g_h16p[3 * NP * 32];

__device__ int g_rp_ap[NA + 1];
__device__ int g_rp_pa[NP + 1];
__device__ int g_rp_pp[NP + 1];
__device__ int g_ts_ap[NE];
__device__ int g_ts_pa[NE];
__device__ int g_ts_pp[NE];
__device__ int g_cntA[NA];
__device__ int g_cntP1[NP];
__device__ int g_cntP2[NP];
__device__ int g_bsum[3 * 64];

// x-based attention scalars, all hops precomputed
__device__ float g_x1ap[3 * NA], g_x2ap[3 * NA];
__device__ float g_x1pa[3 * NP], g_x2pa[3 * NP], g_x1pp[3 * NP], g_x2pp[3 * NP];
// h-based scalars, double buffered
__device__ float g_h1pa[2 * NA];
__device__ float g_h1ap[2 * NP], g_h1pp[2 * NP];

// ---------------- helpers ----------------
__device__ __forceinline__ const __half2* bufA16(int c) { return g_h16a + (size_t)c * NA * 32; }
__device__ __forceinline__ const __half2* bufP16(int c) { return g_h16p + (size_t)c * NP * 32; }
__device__ __forceinline__ float eluf(float v) { return v > 0.f ? v : expm1f(v); }
__device__ __forceinline__ float lrelu_exp(float sc) {
    sc = sc >= 0.f ? sc : 0.2f * sc;
    return __expf(sc);
}
__device__ __forceinline__ float wred32(float v) {
    v += __shfl_down_sync(0xffffffffu, v, 16);
    v += __shfl_down_sync(0xffffffffu, v, 8);
    v += __shfl_down_sync(0xffffffffu, v, 4);
    v += __shfl_down_sync(0xffffffffu, v, 2);
    v += __shfl_down_sync(0xffffffffu, v, 1);
    return v;
}
__device__ __forceinline__ float wred16(float v) {
    v += __shfl_down_sync(0xffffffffu, v, 8, 16);
    v += __shfl_down_sync(0xffffffffu, v, 4, 16);
    v += __shfl_down_sync(0xffffffffu, v, 2, 16);
    v += __shfl_down_sync(0xffffffffu, v, 1, 16);
    return v;
}
__device__ __forceinline__ unsigned long long pk2(float lo, float hi) {
    unsigned long long r;
    asm("mov.b64 %0, {%1, %2};" : "=l"(r) : "f"(lo), "f"(hi));
    return r;
}
__device__ __forceinline__ void up2(unsigned long long v, float& lo, float& hi) {
    asm("mov.b64 {%0, %1}, %2;" : "=f"(lo), "=f"(hi) : "l"(v));
}
__device__ __forceinline__ void ffma2(unsigned long long& d, unsigned long long a, unsigned long long b) {
    asm("fma.rn.f32x2 %0, %1, %2, %0;" : "+l"(d) : "l"(a), "l"(b));
}
__device__ __forceinline__ uint2 pack_h4(float x, float y, float z, float w) {
    __half2 q0 = __floats2half2_rn(x, y);
    __half2 q1 = __floats2half2_rn(z, w);
    uint2 st;
    st.x = *reinterpret_cast<unsigned*>(&q0);
    st.y = *reinterpret_cast<unsigned*>(&q1);
    return st;
}

// ---------------- CSR build ----------------
__global__ void zero_cnt_kernel() {
    int i = blockIdx.x * blockDim.x + threadIdx.x;
    int stride = gridDim.x * blockDim.x;
    for (; i < NA + 2 * NP; i += stride) {
        if (i < NA) g_cntA[i] = 0;
        else if (i < NA + NP) g_cntP1[i - NA] = 0;
        else g_cntP2[i - NA - NP] = 0;
    }
}

__global__ void hist_kernel(const int* __restrict__ ap_s,
                            const int* __restrict__ pa_s,
                            const int* __restrict__ pp_s) {
    const int Q = NE / 4;   // int4 chunks per relation
    int i = blockIdx.x * blockDim.x + threadIdx.x;
    int stride = gridDim.x * blockDim.x;
    for (; i < 3 * Q; i += stride) {
        int4 v;
        int* cnt;
        if (i < Q)          { v = ((const int4*)ap_s)[i];        cnt = g_cntA;  }
        else if (i < 2 * Q) { v = ((const int4*)pa_s)[i - Q];    cnt = g_cntP1; }
        else                { v = ((const int4*)pp_s)[i - 2 * Q]; cnt = g_cntP2; }
        atomicAdd(&cnt[v.x], 1);
        atomicAdd(&cnt[v.y], 1);
        atomicAdd(&cnt[v.z], 1);
        atomicAdd(&cnt[v.w], 1);
    }
}

__device__ __forceinline__ void rel_of(int b, int& rel, int& chunk) {
    if (b < NCH_A)              { rel = 0; chunk = b; }
    else if (b < NCH_A + NCH_P) { rel = 1; chunk = b - NCH_A; }
    else                        { rel = 2; chunk = b - NCH_A - NCH_P; }
}

__global__ void scan_passA() {
    int rel, chunk; rel_of(blockIdx.x, rel, chunk);
    const int* cnt = rel == 0 ? g_cntA : (rel == 1 ? g_cntP1 : g_cntP2);
    int n = rel == 0 ? NA : NP;
    int base = chunk * CH;
    int s = 0;
    #pragma unroll
    for (int j = 0; j < 8; j++) {
        int i = base + threadIdx.x + 256 * j;
        if (i < n) s += cnt[i];
    }
    #pragma unroll
    for (int o = 16; o; o >>= 1) s += __shfl_down_sync(0xffffffffu, s, o);
    __shared__ int sh[8];
    int lane = threadIdx.x & 31, wid = threadIdx.x >> 5;
    if (lane == 0) sh[wid] = s;
    __syncthreads();
    if (wid == 0) {
        int t = (lane < 8) ? sh[lane] : 0;
        #pragma unroll
        for (int o = 4; o; o >>= 1) t += __shfl_down_sync(0xffffffffu, t, o);
        if (lane == 0) g_bsum[rel * 64 + chunk] = t;
    }
}

__global__ void scan_passB() {   // 1 block, 96 threads
    int wid = threadIdx.x >> 5, lane = threadIdx.x & 31;
    if (wid < 3) {
        int nch = (wid == 0) ? NCH_A : NCH_P;
        int carry = 0;
        #pragma unroll
        for (int c0 = 0; c0 < 64; c0 += 32) {
            int idx = c0 + lane;
            int v = (idx < nch) ? g_bsum[wid * 64 + idx] : 0;
            int x = v;
            #pragma unroll
            for (int o = 1; o < 32; o <<= 1) {
                int y = __shfl_up_sync(0xffffffffu, x, o);
                if (lane >= o) x += y;
            }
            g_bsum[wid * 64 + idx] = carry + x - v;   // exclusive
            carry += __shfl_sync(0xffffffffu, x, 31);
        }
        if (lane == 0) {
            if (wid == 0)      g_rp_ap[NA] = carry;
            else if (wid == 1) g_rp_pa[NP] = carry;
            else               g_rp_pp[NP] = carry;
        }
    }
}

__global__ void scan_passC() {   // re-scan chunk, write rp, zero cnt
    int rel, chunk; rel_of(blockIdx.x, rel, chunk);
    int* cnt; int* rp; int n;
    if (rel == 0)      { cnt = g_cntA;  rp = g_rp_ap; n = NA; }
    else if (rel == 1) { cnt = g_cntP1; rp = g_rp_pa; n = NP; }
    else               { cnt = g_cntP2; rp = g_rp_pp; n = NP; }
    int tid = threadIdx.x, lane = tid & 31, wid = tid >> 5;
    int i0 = chunk * CH + tid * 8;
    int v[8];
    #pragma unroll
    for (int j = 0; j < 8; j++) v[j] = (i0 + j < n) ? cnt[i0 + j] : 0;
    int s = 0;
    #pragma unroll
    for (int j = 0; j < 8; j++) { int t = v[j]; v[j] = s; s += t; }   // local exclusive, s=sum
    int x = s;
    #pragma unroll
    for (int o = 1; o < 32; o <<= 1) {
        int y = __shfl_up_sync(0xffffffffu, x, o);
        if (lane >= o) x += y;
    }
    __shared__ int wsum[8];
    if (lane == 31) wsum[wid] = x;
    __syncthreads();
    if (wid == 0 && lane < 8) {
        int t = wsum[lane];
        int xx = t;
        #pragma unroll
        for (int o = 1; o < 8; o <<= 1) {
            int y = __shfl_up_sync(0xffu, xx, o);
            if (lane >= o) xx += y;
        }
        wsum[lane] = xx - t;   // exclusive warp offsets
    }
    __syncthreads();
    int off = g_bsum[rel * 64 + chunk] + wsum[wid] + (x - s);
    #pragma unroll
    for (int j = 0; j < 8; j++) {
        int i = i0 + j;
        if (i < n) { rp[i] = off + v[j]; cnt[i] = 0; }
    }
}

__global__ void scatter_kernel(const int* __restrict__ ap_s, const int* __restrict__ ap_t,
                               const int* __restrict__ pa_s, const int* __restrict__ pa_t,
                               const int* __restrict__ pp_s, const int* __restrict__ pp_t) {
    const int Q = NE / 4;
    int i = blockIdx.x * blockDim.x + threadIdx.x;
    int stride = gridDim.x * blockDim.x;
    for (; i < 3 * Q; i += stride) {
        int4 sv, tv;
        int* cnt; const int* rp; int* ts;
        if (i < Q) {
            sv = ((const int4*)ap_s)[i]; tv = ((const int4*)ap_t)[i];
            cnt = g_cntA; rp = g_rp_ap; ts = g_ts_ap;
        } else if (i < 2 * Q) {
            sv = ((const int4*)pa_s)[i - Q]; tv = ((const int4*)pa_t)[i - Q];
            cnt = g_cntP1; rp = g_rp_pa; ts = g_ts_pa;
        } else {
            sv = ((const int4*)pp_s)[i - 2 * Q]; tv = ((const int4*)pp_t)[i - 2 * Q];
            cnt = g_cntP2; rp = g_rp_pp; ts = g_ts_pp;
        }
        int p0 = rp[sv.x] + atomicAdd(&cnt[sv.x], 1); ts[p0] = tv.x;
        int p1 = rp[sv.y] + atomicAdd(&cnt[sv.y], 1); ts[p1] = tv.y;
        int p2 = rp[sv.z] + atomicAdd(&cnt[sv.z], 1); ts[p2] = tv.z;
        int p3 = rp[sv.w] + atomicAdd(&cnt[sv.w], 1); ts[p3] = tv.w;
    }
}

// ---------------- projection GEMM, 128 threads, 128x64 tile, 8x8/thread, FFMA2 ----
__global__ __launch_bounds__(128) void proj_gemm2(
    const float* __restrict__ XA, const float* __restrict__ WA, const float* __restrict__ bA,
    const float* __restrict__ XP, const float* __restrict__ WP, const float* __restrict__ bP) {
    __shared__ __align__(16) float xs[32 * XS_STRIDE];
    __shared__ __align__(16) float ws[32 * 64];
    int b = blockIdx.x;
    const float* X; const float* W; const float* bias; float* Y; __half2* Y16; int N, K, nb;
    if (b < GEMM_A_BLOCKS) {
        X = XA; W = WA; bias = bA; Y = g_xa; N = NA; K = DA; nb = b * 128;
        Y16 = g_h16a + (size_t)2 * NA * 32;
    } else {
        b -= GEMM_A_BLOCKS;
        X = XP; W = WP; bias = bP; Y = g_xp; N = NP; K = DP; nb = b * 128;
        Y16 = g_h16p + (size_t)2 * NP * 32;
    }

    int tid = threadIdx.x;
    int tn = tid & 7, tm = tid >> 3;

    unsigned long long acc[8][4];
    #pragma unroll
    for (int r = 0; r < 8; r++)
        #pragma unroll
        for (int p = 0; p < 4; p++) acc[r][p] = 0ull;

    for (int kc = 0; kc < K; kc += 32) {
        #pragma unroll
        for (int j = 0; j < 8; j++) {
            int idx = tid + 128 * j;
            int node = idx >> 3, kq = idx & 7;
            int gn = nb + node;
            float4 v = (gn < N) ? *(const float4*)&X[(size_t)gn * K + kc + kq * 4]
                                : make_float4(0.f, 0.f, 0.f, 0.f);
            int kb = kq * 4;
            xs[(kb + 0) * XS_STRIDE + node] = v.x;
            xs[(kb + 1) * XS_STRIDE + node] = v.y;
            xs[(kb + 2) * XS_STRIDE + node] = v.z;
            xs[(kb + 3) * XS_STRIDE + node] = v.w;
        }
        #pragma unroll
        for (int j = 0; j < 4; j++) {
            int idx = tid + 128 * j;
            int row = idx >> 4, cq = idx & 15;
            *(float4*)&ws[row * 64 + cq * 4] = *(const float4*)&W[(size_t)(kc + row) * 64 + cq * 4];
        }
        __syncthreads();
        #pragma unroll
        for (int kk = 0; kk < 32; kk++) {
            float4 xv0 = *(const float4*)&xs[kk * XS_STRIDE + tm * 4];
            float4 xv1 = *(const float4*)&xs[kk * XS_STRIDE + 64 + tm * 4];
            float4 wv0 = *(const float4*)&ws[kk * 64 + tn * 4];
            float4 wv1 = *(const float4*)&ws[kk * 64 + 32 + tn * 4];
            unsigned long long wp0 = pk2(wv0.x, wv0.y);
            unsigned long long wp1 = pk2(wv0.z, wv0.w);
            unsigned long long wp2 = pk2(wv1.x, wv1.y);
            unsigned long long wp3 = pk2(wv1.z, wv1.w);
            float xr[8] = {xv0.x, xv0.y, xv0.z, xv0.w, xv1.x, xv1.y, xv1.z, xv1.w};
            #pragma unroll
            for (int r = 0; r < 8; r++) {
                unsigned long long xd = pk2(xr[r], xr[r]);
                ffma2(acc[r][0], xd, wp0);
                ffma2(acc[r][1], xd, wp1);
                ffma2(acc[r][2], xd, wp2);
                ffma2(acc[r][3], xd, wp3);
            }
        }
        __syncthreads();
    }

    float4 bv0 = *(const float4*)&bias[tn * 4];
    float4 bv1 = *(const float4*)&bias[32 + tn * 4];
    #pragma unroll
    for (int r = 0; r < 8; r++) {
        int node = nb + ((r < 4) ? (tm * 4 + r) : (64 + tm * 4 + r - 4));
        if (node < N) {
            float f0, f1, f2, f3, f4, f5, f6, f7;
            up2(acc[r][0], f0, f1);
            up2(acc[r][1], f2, f3);
            up2(acc[r][2], f4, f5);
            up2(acc[r][3], f6, f7);
            float4 o0, o1;
            o0.x = fmaxf(f0 + bv0.x, 0.f); o0.y = fmaxf(f1 + bv0.y, 0.f);
            o0.z = fmaxf(f2 + bv0.z, 0.f); o0.w = fmaxf(f3 + bv0.w, 0.f);
            o1.x = fmaxf(f4 + bv1.x, 0.f); o1.y = fmaxf(f5 + bv1.y, 0.f);
            o1.z = fmaxf(f6 + bv1.z, 0.f); o1.w = fmaxf(f7 + bv1.w, 0.f);
            *(float4*)&Y[(size_t)node * 64 + tn * 4] = o0;
            *(float4*)&Y[(size_t)node * 64 + 32 + tn * 4] = o1;
            // fp16 mirror (x is hop-0 h)
            uint2 m0 = pack_h4(o0.x, o0.y, o0.z, o0.w);
            uint2 m1 = pack_h4(o1.x, o1.y, o1.z, o1.w);
            *reinterpret_cast<uint2*>(&Y16[(size_t)node * 32 + tn * 2]) = m0;
            *reinterpret_cast<uint2*>(&Y16[(size_t)node * 32 + 16 + tn * 2]) = m1;
        }
    }
}

// ---------------- upfront scalar projections (all hops, x-based + hop-0 h-based) ----
__global__ void sproj0_kernel(const float* __restrict__ a1ap, const float* __restrict__ a2ap,
                              const float* __restrict__ a1pa, const float* __restrict__ a2pa,
                              const float* __restrict__ a1pp, const float* __restrict__ a2pp) {
    int gw = (blockIdx.x * blockDim.x + threadIdx.x) >> 5;
    int lane = threadIdx.x & 31;
    if (gw < NA) {
        int n = gw;
        float x0 = g_xa[(size_t)n * 64 + lane], x1 = g_xa[(size_t)n * 64 + 32 + lane];
        #pragma unroll
        for (int h = 0; h < 3; h++) {
            float d1 = wred32(fmaf(x0, a1ap[h * 64 + lane], x1 * a1ap[h * 64 + 32 + lane]));
            float d2 = wred32(fmaf(x0, a2ap[h * 64 + lane], x1 * a2ap[h * 64 + 32 + lane]));
            if (lane == 0) { g_x1ap[h * NA + n] = d1; g_x2ap[h * NA + n] = d2; }
        }
        float d3 = wred32(fmaf(x0, a2pa[lane], x1 * a2pa[32 + lane]));
        if (lane == 0) g_h1pa[n] = d3;   // buffer 0
    } else {
        int n = gw - NA;
        float x0 = g_xp[(size_t)n * 64 + lane], x1 = g_xp[(size_t)n * 64 + 32 + lane];
        #pragma unroll
        for (int h = 0; h < 3; h++) {
            float d1 = wred32(fmaf(x0, a1pa[h * 64 + lane], x1 * a1pa[h * 64 + 32 + lane]));
            float d2 = wred32(fmaf(x0, a2pa[h * 64 + lane], x1 * a2pa[h * 64 + 32 + lane]));
            float d3 = wred32(fmaf(x0, a1pp[h * 64 + lane], x1 * a1pp[h * 64 + 32 + lane]));
            float d4 = wred32(fmaf(x0, a2pp[h * 64 + lane], x1 * a2pp[h * 64 + 32 + lane]));
            if (lane == 0) {
                g_x1pa[h * NP + n] = d1; g_x2pa[h * NP + n] = d2;
                g_x1pp[h * NP + n] = d3; g_x2pp[h * NP + n] = d4;
            }
        }
        float d5 = wred32(fmaf(x0, a2ap[lane], x1 * a2ap[32 + lane]));
        float d6 = wred32(fmaf(x0, a2pp[lane], x1 * a2pp[32 + lane]));
        if (lane == 0) { g_h1ap[n] = d5; g_h1pp[n] = d6; }   // buffer 0
    }
}

// ---------------- merged edge aggregation (fp16 gathers, fp32 math) ----------------
__device__ __forceinline__ void relation_accum16(const int* __restrict__ rp,
                                                 const int* __restrict__ ts,
                                                 const __half2* __restrict__ h16,
                                                 const float* __restrict__ h1arr,
                                                 float x1, int n, int sub,
                                                 float4& acc, float& div) {
    int e = rp[n], end = rp[n + 1];
    #pragma unroll 4
    for (; e < end; ++e) {
        int t = __ldg(&ts[e]);
        float w = lrelu_exp(x1 + __ldg(&h1arr[t]));
        uint2 rv = *reinterpret_cast<const uint2*>(&h16[(size_t)t * 32 + (sub << 1)]);
        __half2 a = *reinterpret_cast<const __half2*>(&rv.x);
        __half2 bb = *reinterpret_cast<const __half2*>(&rv.y);
        float2 f0 = __half22float2(a);
        float2 f1 = __half22float2(bb);
        acc.x = fmaf(w, f0.x, acc.x);
        acc.y = fmaf(w, f0.y, acc.y);
        acc.z = fmaf(w, f1.x, acc.z);
        acc.w = fmaf(w, f1.y, acc.w);
        div += w;
    }
}

__global__ void agg_kernel(int curA, int curP, int nxt, int h1cur, int h1nxt, int hop, int last,
                           const float* __restrict__ a2pa_nx,
                           const float* __restrict__ a2ap_nx,
                           const float* __restrict__ a2pp_nx) {
    int lane = threadIdx.x & 31;
    int sub = lane & 15;
    int half = lane >> 4;
    if (blockIdx.x < BA_BLOCKS) {
        int warp = (blockIdx.x * blockDim.x + threadIdx.x) >> 5;
        int n = warp * 2 + half;            // exact cover of NA
        const __half2* __restrict__ h = bufP16(curP);
        const float* __restrict__ h1 = g_h1ap + (size_t)h1cur * NP;
        float x1 = g_x1ap[hop * NA + n];
        float4 acc = {0.f, 0.f, 0.f, 0.f};
        float div = 0.f;
        relation_accum16(g_rp_ap, g_ts_ap, h, h1, x1, n, sub, acc, div);
        float w2 = lrelu_exp(x1 + g_x2ap[hop * NA + n]);
        const float4 xv = *reinterpret_cast<const float4*>(&g_xa[(size_t)n * 64 + (sub << 2)]);
        acc.x = fmaf(w2, xv.x, acc.x); acc.y = fmaf(w2, xv.y, acc.y);
        acc.z = fmaf(w2, xv.z, acc.z); acc.w = fmaf(w2, xv.w, acc.w);
        div += w2;
        float inv = 1.f / div;
        float4 r;
        r.x = eluf(acc.x * inv); r.y = eluf(acc.y * inv);
        r.z = eluf(acc.z * inv); r.w = eluf(acc.w * inv);
        if (last) {
            // fp32 output for fc2
            *reinterpret_cast<float4*>(&g_ha[(size_t)n * 64 + (sub << 2)]) = r;
        } else {
            uint2 st = pack_h4(r.x, r.y, r.z, r.w);
            *reinterpret_cast<uint2*>(&g_h16a[((size_t)nxt * NA + n) * 32 + (sub << 1)]) = st;
            const float4 va = *(const float4*)&a2pa_nx[sub << 2];
            float p = r.x * va.x + r.y * va.y + r.z * va.z + r.w * va.w;
            p = wred16(p);
            if (sub == 0) g_h1pa[(size_t)h1nxt * NA + n] = p;
        }
    } else {
        int warp = ((blockIdx.x - BA_BLOCKS) * blockDim.x + threadIdx.x) >> 5;
        int n = warp * 2 + half;            // exact cover of NP
        const __half2* __restrict__ hA = bufA16(curA);
        const __half2* __restrict__ hP = bufP16(curP);
        const float* __restrict__ h1a = g_h1pa + (size_t)h1cur * NA;
        const float* __restrict__ h1p = g_h1pp + (size_t)h1cur * NP;
        float x1a = g_x1pa[hop * NP + n];
        float x1p = g_x1pp[hop * NP + n];
        float4 acc1 = {0.f, 0.f, 0.f, 0.f}, acc2 = {0.f, 0.f, 0.f, 0.f};
        float div1 = 0.f, div2 = 0.f;
        relation_accum16(g_rp_pa, g_ts_pa, hA, h1a, x1a, n, sub, acc1, div1);
        relation_accum16(g_rp_pp, g_ts_pp, hP, h1p, x1p, n, sub, acc2, div2);
        const float4 xv = *reinterpret_cast<const float4*>(&g_xp[(size_t)n * 64 + (sub << 2)]);
        float w2a = lrelu_exp(x1a + g_x2pa[hop * NP + n]);
        float w2p = lrelu_exp(x1p + g_x2pp[hop * NP + n]);
        acc1.x = fmaf(w2a, xv.x, acc1.x); acc1.y = fmaf(w2a, xv.y, acc1.y);
        acc1.z = fmaf(w2a, xv.z, acc1.z); acc1.w = fmaf(w2a, xv.w, acc1.w);
        div1 += w2a;
        acc2.x = fmaf(w2p, xv.x, acc2.x); acc2.y = fmaf(w2p, xv.y, acc2.y);
        acc2.z = fmaf(w2p, xv.z, acc2.z); acc2.w = fmaf(w2p, xv.w, acc2.w);
        div2 += w2p;
        float i1 = 1.f / div1, i2 = 1.f / div2;
        float4 r;
        r.x = eluf(0.5f * (acc1.x * i1 + acc2.x * i2));
        r.y = eluf(0.5f * (acc1.y * i1 + acc2.y * i2));
        r.z = eluf(0.5f * (acc1.z * i1 + acc2.z * i2));
        r.w = eluf(0.5f * (acc1.w * i1 + acc2.w * i2));
        if (!last) {
            uint2 st = pack_h4(r.x, r.y, r.z, r.w);
            *reinterpret_cast<uint2*>(&g_h16p[((size_t)nxt * NP + n) * 32 + (sub << 1)]) = st;
            const float4 va = *(const float4*)&a2ap_nx[sub << 2];
            const float4 vp = *(const float4*)&a2pp_nx[sub << 2];
            float p1 = r.x * va.x + r.y * va.y + r.z * va.z + r.w * va.w;
            float p2 = r.x * vp.x + r.y * vp.y + r.z * vp.z + r.w * vp.w;
            p1 = wred16(p1);
            p2 = wred16(p2);
            if (sub == 0) {
                g_h1ap[(size_t)h1nxt * NP + n] = p1;
                g_h1pp[(size_t)h1nxt * NP + n] = p2;
            }
        }
    }
}

// ---------------- final projection ----------------
__global__ void final_fc2_kernel(const float* __restrict__ W,
                                 const float* __restrict__ b,
                                 float* __restrict__ out) {
    __shared__ float ws[64 * 16];
    int tid = threadIdx.x;
    for (int i = tid; i < 64 * 16; i += blockDim.x) ws[i] = W[i];
    __syncthreads();
    const float* h = g_ha;
    int j = tid & 15, nl = tid >> 4;
    for (int n = blockIdx.x * 16 + nl; n < NA; n += gridDim.x * 16) {
        float acc = b[j];
        #pragma unroll 8
        for (int k = 0; k < 64; k++) acc = fmaf(h[(size_t)n * 64 + k], ws[k * 16 + j], acc);
        out[(size_t)n * 16 + j] = acc;
    }
}

// ---------------- launch ----------------
extern "C" void kernel_launch(void* const* d_in, const int* in_sizes, int n_in,
                              void* d_out, int out_size) {
    const float* x_a   = (const float*)d_in[0];
    const float* x_p   = (const float*)d_in[1];
    const int* ap_s    = (const int*)d_in[2];
    const int* ap_t    = (const int*)d_in[3];
    const int* pa_s    = (const int*)d_in[4];
    const int* pa_t    = (const int*)d_in[5];
    const int* pp_s    = (const int*)d_in[6];
    const int* pp_t    = (const int*)d_in[7];
    const float* fc1aw = (const float*)d_in[8];
    const float* fc1ab = (const float*)d_in[9];
    const float* fc1pw = (const float*)d_in[10];
    const float* fc1pb = (const float*)d_in[11];
    const float* fc2w  = (const float*)d_in[12];
    const float* fc2b  = (const float*)d_in[13];
    const float* a1ap  = (const float*)d_in[14];
    const float* a2ap  = (const float*)d_in[15];
    const float* a1pa  = (const float*)d_in[16];
    const float* a2pa  = (const float*)d_in[17];
    const float* a1pp  = (const float*)d_in[18];
    const float* a2pp  = (const float*)d_in[19];
    float* out = (float*)d_out;

    // one-time setup of the side stream + fork/join events (host-side resources,
    // created on the first, uncaptured call; device work is identical every call)
    static cudaStream_t s2 = nullptr;
    static cudaEvent_t evF = nullptr, evJ = nullptr;
    if (s2 == nullptr) {
        cudaStreamCreateWithFlags(&s2, cudaStreamNonBlocking);
        cudaEventCreateWithFlags(&evF, cudaEventDisableTiming);
        cudaEventCreateWithFlags(&evJ, cudaEventDisableTiming);
    }

    // ---- fork: projection chain on s2, CSR chain on the main stream ----
    cudaEventRecord(evF, 0);
    cudaStreamWaitEvent(s2, evF, 0);

    proj_gemm2<<<GEMM_A_BLOCKS + GEMM_P_BLOCKS, 128, 0, s2>>>(x_a, fc1aw, fc1ab, x_p, fc1pw, fc1pb);
    sproj0_kernel<<<(NA + NP) / 8, 256, 0, s2>>>(a1ap, a2ap, a1pa, a2pa, a1pp, a2pp);
    cudaEventRecord(evJ, s2);

    // CSR build (main stream, overlapped with the projection chain)
    zero_cnt_kernel<<<977, 256>>>();
    hist_kernel<<<1024, 256>>>(ap_s, pa_s, pp_s);
    scan_passA<<<NBLK_SCAN, 256>>>();
    scan_passB<<<1, 96>>>();
    scan_passC<<<NBLK_SCAN, 256>>>();   // also zeroes cnt
    scatter_kernel<<<1500, 256>>>(ap_s, ap_t, pa_s, pa_t, pp_s, pp_t);

    // ---- join: agg needs CSR + projections + scalars ----
    cudaStreamWaitEvent(0, evJ, 0);

    // hops
    int curA = 2, curP = 2, nxt = 0, h1cur = 0, h1nxt = 1;
    for (int hop = 0; hop < 3; hop++) {
        int last = (hop == 2);
        int nh = last ? 2 : (hop + 1);   // next-hop a2 vectors (unused when last)
        agg_kernel<<<BA_BLOCKS + BP_BLOCKS, 256>>>(curA, curP, nxt, h1cur, h1nxt, hop, last,
                                                   a2pa + 64 * nh, a2ap + 64 * nh, a2pp + 64 * nh);
        curA = nxt; curP = nxt;
        nxt ^= 1;
        int t = h1cur; h1cur = h1nxt; h1nxt = t;
    }

    final_fc2_kernel<<<3125, 256>>>(fc2w, fc2b, out);
}

// round 9
// speedup vs baseline: 1.1593x; 1.1288x over previous
#include <cuda_runtime.h>
#include <cuda_fp16.h>
#include <cuda_bf16.h>
#include <math.h>

#define NA 50000
#define NP 100000
#define DA 512
#define DP 256
#define HID 64
#define NOUT 16
#define NE 2000000
#define CH 2048
#define NCH_A 25
#define NCH_P 49
#define NBLK_SCAN (NCH_A + 2*NCH_P)   // 123
#define BA_BLOCKS 3125   // NA/2 nodes -> 25000 warps
#define BP_BLOCKS 6250
#define GEMM_A_BLOCKS 391
#define GEMM_P_BLOCKS 782
#define XS_STRIDE 132

// ---------------- scratch ----------------
__device__ float g_xa[NA * HID];
__device__ float g_xp[NP * HID];
// fp16 gather mirrors; buffer index 2 == x mirror
__device__ __align__(16) __half2 g_h16a[3 * NA * 32];
__device__ __align__(16) __half2 g_h16p[3 * NP * 32];

__device__ int g_rp_ap[NA + 1];
__device__ int g_rp_pa[NP + 1];
__device__ int g_rp_pp[NP + 1];
__device__ int g_ts_ap[NE];
__device__ int g_ts_pa[NE];
__device__ int g_ts_pp[NE];
__device__ int g_cntA[NA];
__device__ int g_cntP1[NP];
__device__ int g_cntP2[NP];
__device__ int g_bsum[3 * 64];

// x-based attention scalars, all hops precomputed
__device__ float g_x1ap[3 * NA], g_x2ap[3 * NA];
__device__ float g_x1pa[3 * NP], g_x2pa[3 * NP], g_x1pp[3 * NP], g_x2pp[3 * NP];
// h-based scalars, double buffered
__device__ float g_h1pa[2 * NA];
__device__ float g_h1ap[2 * NP], g_h1pp[2 * NP];

// ---------------- helpers ----------------
__device__ __forceinline__ const __half2* bufA16(int c) { return g_h16a + (size_t)c * NA * 32; }
__device__ __forceinline__ const __half2* bufP16(int c) { return g_h16p + (size_t)c * NP * 32; }
__device__ __forceinline__ float eluf(float v) { return v > 0.f ? v : expm1f(v); }
__device__ __forceinline__ float lrelu_exp(float sc) {
    sc = sc >= 0.f ? sc : 0.2f * sc;
    return __expf(sc);
}
__device__ __forceinline__ float wred32(float v) {
    v += __shfl_down_sync(0xffffffffu, v, 16);
    v += __shfl_down_sync(0xffffffffu, v, 8);
    v += __shfl_down_sync(0xffffffffu, v, 4);
    v += __shfl_down_sync(0xffffffffu, v, 2);
    v += __shfl_down_sync(0xffffffffu, v, 1);
    return v;
}
__device__ __forceinline__ float wred16(float v) {
    v += __shfl_down_sync(0xffffffffu, v, 8, 16);
    v += __shfl_down_sync(0xffffffffu, v, 4, 16);
    v += __shfl_down_sync(0xffffffffu, v, 2, 16);
    v += __shfl_down_sync(0xffffffffu, v, 1, 16);
    return v;
}
__device__ __forceinline__ unsigned long long pk2(float lo, float hi) {
    unsigned long long r;
    asm("mov.b64 %0, {%1, %2};" : "=l"(r) : "f"(lo), "f"(hi));
    return r;
}
__device__ __forceinline__ void up2(unsigned long long v, float& lo, float& hi) {
    asm("mov.b64 {%0, %1}, %2;" : "=f"(lo), "=f"(hi) : "l"(v));
}
__device__ __forceinline__ void ffma2(unsigned long long& d, unsigned long long a, unsigned long long b) {
    asm("fma.rn.f32x2 %0, %1, %2, %0;" : "+l"(d) : "l"(a), "l"(b));
}
__device__ __forceinline__ uint2 pack_h4(float x, float y, float z, float w) {
    __half2 q0 = __floats2half2_rn(x, y);
    __half2 q1 = __floats2half2_rn(z, w);
    uint2 st;
    st.x = *reinterpret_cast<unsigned*>(&q0);
    st.y = *reinterpret_cast<unsigned*>(&q1);
    return st;
}

// ---------------- CSR build ----------------
__global__ void zero_cnt_kernel() {
    int i = blockIdx.x * blockDim.x + threadIdx.x;
    int stride = gridDim.x * blockDim.x;
    for (; i < NA + 2 * NP; i += stride) {
        if (i < NA) g_cntA[i] = 0;
        else if (i < NA + NP) g_cntP1[i - NA] = 0;
        else g_cntP2[i - NA - NP] = 0;
    }
}

__global__ void hist_kernel(const int* __restrict__ ap_s,
                            const int* __restrict__ pa_s,
                            const int* __restrict__ pp_s) {
    const int Q = NE / 4;
    int i = blockIdx.x * blockDim.x + threadIdx.x;
    int stride = gridDim.x * blockDim.x;
    for (; i < 3 * Q; i += stride) {
        int4 v;
        int* cnt;
        if (i < Q)          { v = ((const int4*)ap_s)[i];        cnt = g_cntA;  }
        else if (i < 2 * Q) { v = ((const int4*)pa_s)[i - Q];    cnt = g_cntP1; }
        else                { v = ((const int4*)pp_s)[i - 2 * Q]; cnt = g_cntP2; }
        atomicAdd(&cnt[v.x], 1);
        atomicAdd(&cnt[v.y], 1);
        atomicAdd(&cnt[v.z], 1);
        atomicAdd(&cnt[v.w], 1);
    }
}

__device__ __forceinline__ void rel_of(int b, int& rel, int& chunk) {
    if (b < NCH_A)              { rel = 0; chunk = b; }
    else if (b < NCH_A + NCH_P) { rel = 1; chunk = b - NCH_A; }
    else                        { rel = 2; chunk = b - NCH_A - NCH_P; }
}

__global__ void scan_passA() {
    int rel, chunk; rel_of(blockIdx.x, rel, chunk);
    const int* cnt = rel == 0 ? g_cntA : (rel == 1 ? g_cntP1 : g_cntP2);
    int n = rel == 0 ? NA : NP;
    int base = chunk * CH;
    int s = 0;
    #pragma unroll
    for (int j = 0; j < 8; j++) {
        int i = base + threadIdx.x + 256 * j;
        if (i < n) s += cnt[i];
    }
    #pragma unroll
    for (int o = 16; o; o >>= 1) s += __shfl_down_sync(0xffffffffu, s, o);
    __shared__ int sh[8];
    int lane = threadIdx.x & 31, wid = threadIdx.x >> 5;
    if (lane == 0) sh[wid] = s;
    __syncthreads();
    if (wid == 0) {
        int t = (lane < 8) ? sh[lane] : 0;
        #pragma unroll
        for (int o = 4; o; o >>= 1) t += __shfl_down_sync(0xffffffffu, t, o);
        if (lane == 0) g_bsum[rel * 64 + chunk] = t;
    }
}

__global__ void scan_passB() {   // 1 block, 96 threads
    int wid = threadIdx.x >> 5, lane = threadIdx.x & 31;
    if (wid < 3) {
        int nch = (wid == 0) ? NCH_A : NCH_P;
        int carry = 0;
        #pragma unroll
        for (int c0 = 0; c0 < 64; c0 += 32) {
            int idx = c0 + lane;
            int v = (idx < nch) ? g_bsum[wid * 64 + idx] : 0;
            int x = v;
            #pragma unroll
            for (int o = 1; o < 32; o <<= 1) {
                int y = __shfl_up_sync(0xffffffffu, x, o);
                if (lane >= o) x += y;
            }
            g_bsum[wid * 64 + idx] = carry + x - v;   // exclusive
            carry += __shfl_sync(0xffffffffu, x, 31);
        }
        if (lane == 0) {
            if (wid == 0)      g_rp_ap[NA] = carry;
            else if (wid == 1) g_rp_pa[NP] = carry;
            else               g_rp_pp[NP] = carry;
        }
    }
}

__global__ void scan_passC() {   // re-scan chunk, write rp, zero cnt
    int rel, chunk; rel_of(blockIdx.x, rel, chunk);
    int* cnt; int* rp; int n;
    if (rel == 0)      { cnt = g_cntA;  rp = g_rp_ap; n = NA; }
    else if (rel == 1) { cnt = g_cntP1; rp = g_rp_pa; n = NP; }
    else               { cnt = g_cntP2; rp = g_rp_pp; n = NP; }
    int tid = threadIdx.x, lane = tid & 31, wid = tid >> 5;
    int i0 = chunk * CH + tid * 8;
    int v[8];
    #pragma unroll
    for (int j = 0; j < 8; j++) v[j] = (i0 + j < n) ? cnt[i0 + j] : 0;
    int s = 0;
    #pragma unroll
    for (int j = 0; j < 8; j++) { int t = v[j]; v[j] = s; s += t; }
    int x = s;
    #pragma unroll
    for (int o = 1; o < 32; o <<= 1) {
        int y = __shfl_up_sync(0xffffffffu, x, o);
        if (lane >= o) x += y;
    }
    __shared__ int wsum[8];
    if (lane == 31) wsum[wid] = x;
    __syncthreads();
    if (wid == 0 && lane < 8) {
        int t = wsum[lane];
        int xx = t;
        #pragma unroll
        for (int o = 1; o < 8; o <<= 1) {
            int y = __shfl_up_sync(0xffu, xx, o);
            if (lane >= o) xx += y;
        }
        wsum[lane] = xx - t;
    }
    __syncthreads();
    int off = g_bsum[rel * 64 + chunk] + wsum[wid] + (x - s);
    #pragma unroll
    for (int j = 0; j < 8; j++) {
        int i = i0 + j;
        if (i < n) { rp[i] = off + v[j]; cnt[i] = 0; }
    }
}

__global__ void scatter_kernel(const int* __restrict__ ap_s, const int* __restrict__ ap_t,
                               const int* __restrict__ pa_s, const int* __restrict__ pa_t,
                               const int* __restrict__ pp_s, const int* __restrict__ pp_t) {
    const int Q = NE / 4;
    int i = blockIdx.x * blockDim.x + threadIdx.x;
    int stride = gridDim.x * blockDim.x;
    for (; i < 3 * Q; i += stride) {
        int4 sv, tv;
        int* cnt; const int* rp; int* ts;
        if (i < Q) {
            sv = ((const int4*)ap_s)[i]; tv = ((const int4*)ap_t)[i];
            cnt = g_cntA; rp = g_rp_ap; ts = g_ts_ap;
        } else if (i < 2 * Q) {
            sv = ((const int4*)pa_s)[i - Q]; tv = ((const int4*)pa_t)[i - Q];
            cnt = g_cntP1; rp = g_rp_pa; ts = g_ts_pa;
        } else {
            sv = ((const int4*)pp_s)[i - 2 * Q]; tv = ((const int4*)pp_t)[i - 2 * Q];
            cnt = g_cntP2; rp = g_rp_pp; ts = g_ts_pp;
        }
        int p0 = rp[sv.x] + atomicAdd(&cnt[sv.x], 1); ts[p0] = tv.x;
        int p1 = rp[sv.y] + atomicAdd(&cnt[sv.y], 1); ts[p1] = tv.y;
        int p2 = rp[sv.z] + atomicAdd(&cnt[sv.z], 1); ts[p2] = tv.z;
        int p3 = rp[sv.w] + atomicAdd(&cnt[sv.w], 1); ts[p3] = tv.w;
    }
}

// ---------------- projection GEMM, 128 threads, 128x64 tile, 8x8/thread, FFMA2 ----
__global__ __launch_bounds__(128) void proj_gemm2(
    const float* __restrict__ XA, const float* __restrict__ WA, const float* __restrict__ bA,
    const float* __restrict__ XP, const float* __restrict__ WP, const float* __restrict__ bP) {
    __shared__ __align__(16) float xs[32 * XS_STRIDE];
    __shared__ __align__(16) float ws[32 * 64];
    int b = blockIdx.x;
    const float* X; const float* W; const float* bias; float* Y; __half2* Y16; int N, K, nb;
    if (b < GEMM_A_BLOCKS) {
        X = XA; W = WA; bias = bA; Y = g_xa; N = NA; K = DA; nb = b * 128;
        Y16 = g_h16a + (size_t)2 * NA * 32;
    } else {
        b -= GEMM_A_BLOCKS;
        X = XP; W = WP; bias = bP; Y = g_xp; N = NP; K = DP; nb = b * 128;
        Y16 = g_h16p + (size_t)2 * NP * 32;
    }

    int tid = threadIdx.x;
    int tn = tid & 7, tm = tid >> 3;

    unsigned long long acc[8][4];
    #pragma unroll
    for (int r = 0; r < 8; r++)
        #pragma unroll
        for (int p = 0; p < 4; p++) acc[r][p] = 0ull;

    for (int kc = 0; kc < K; kc += 32) {
        #pragma unroll
        for (int j = 0; j < 8; j++) {
            int idx = tid + 128 * j;
            int node = idx >> 3, kq = idx & 7;
            int gn = nb + node;
            float4 v = (gn < N) ? *(const float4*)&X[(size_t)gn * K + kc + kq * 4]
                                : make_float4(0.f, 0.f, 0.f, 0.f);
            int kb = kq * 4;
            xs[(kb + 0) * XS_STRIDE + node] = v.x;
            xs[(kb + 1) * XS_STRIDE + node] = v.y;
            xs[(kb + 2) * XS_STRIDE + node] = v.z;
            xs[(kb + 3) * XS_STRIDE + node] = v.w;
        }
        #pragma unroll
        for (int j = 0; j < 4; j++) {
            int idx = tid + 128 * j;
            int row = idx >> 4, cq = idx & 15;
            *(float4*)&ws[row * 64 + cq * 4] = *(const float4*)&W[(size_t)(kc + row) * 64 + cq * 4];
        }
        __syncthreads();
        #pragma unroll
        for (int kk = 0; kk < 32; kk++) {
            float4 xv0 = *(const float4*)&xs[kk * XS_STRIDE + tm * 4];
            float4 xv1 = *(const float4*)&xs[kk * XS_STRIDE + 64 + tm * 4];
            float4 wv0 = *(const float4*)&ws[kk * 64 + tn * 4];
            float4 wv1 = *(const float4*)&ws[kk * 64 + 32 + tn * 4];
            unsigned long long wp0 = pk2(wv0.x, wv0.y);
            unsigned long long wp1 = pk2(wv0.z, wv0.w);
            unsigned long long wp2 = pk2(wv1.x, wv1.y);
            unsigned long long wp3 = pk2(wv1.z, wv1.w);
            float xr[8] = {xv0.x, xv0.y, xv0.z, xv0.w, xv1.x, xv1.y, xv1.z, xv1.w};
            #pragma unroll
            for (int r = 0; r < 8; r++) {
                unsigned long long xd = pk2(xr[r], xr[r]);
                ffma2(acc[r][0], xd, wp0);
                ffma2(acc[r][1], xd, wp1);
                ffma2(acc[r][2], xd, wp2);
                ffma2(acc[r][3], xd, wp3);
            }
        }
        __syncthreads();
    }

    float4 bv0 = *(const float4*)&bias[tn * 4];
    float4 bv1 = *(const float4*)&bias[32 + tn * 4];
    #pragma unroll
    for (int r = 0; r < 8; r++) {
        int node = nb + ((r < 4) ? (tm * 4 + r) : (64 + tm * 4 + r - 4));
        if (node < N) {
            float f0, f1, f2, f3, f4, f5, f6, f7;
            up2(acc[r][0], f0, f1);
            up2(acc[r][1], f2, f3);
            up2(acc[r][2], f4, f5);
            up2(acc[r][3], f6, f7);
            float4 o0, o1;
            o0.x = fmaxf(f0 + bv0.x, 0.f); o0.y = fmaxf(f1 + bv0.y, 0.f);
            o0.z = fmaxf(f2 + bv0.z, 0.f); o0.w = fmaxf(f3 + bv0.w, 0.f);
            o1.x = fmaxf(f4 + bv1.x, 0.f); o1.y = fmaxf(f5 + bv1.y, 0.f);
            o1.z = fmaxf(f6 + bv1.z, 0.f); o1.w = fmaxf(f7 + bv1.w, 0.f);
            *(float4*)&Y[(size_t)node * 64 + tn * 4] = o0;
            *(float4*)&Y[(size_t)node * 64 + 32 + tn * 4] = o1;
            uint2 m0 = pack_h4(o0.x, o0.y, o0.z, o0.w);
            uint2 m1 = pack_h4(o1.x, o1.y, o1.z, o1.w);
            *reinterpret_cast<uint2*>(&Y16[(size_t)node * 32 + tn * 2]) = m0;
            *reinterpret_cast<uint2*>(&Y16[(size_t)node * 32 + 16 + tn * 2]) = m1;
        }
    }
}

// ---------------- upfront scalar projections ----------------
__global__ void sproj0_kernel(const float* __restrict__ a1ap, const float* __restrict__ a2ap,
                              const float* __restrict__ a1pa, const float* __restrict__ a2pa,
                              const float* __restrict__ a1pp, const float* __restrict__ a2pp) {
    int gw = (blockIdx.x * blockDim.x + threadIdx.x) >> 5;
    int lane = threadIdx.x & 31;
    if (gw < NA) {
        int n = gw;
        float x0 = g_xa[(size_t)n * 64 + lane], x1 = g_xa[(size_t)n * 64 + 32 + lane];
        #pragma unroll
        for (int h = 0; h < 3; h++) {
            float d1 = wred32(fmaf(x0, a1ap[h * 64 + lane], x1 * a1ap[h * 64 + 32 + lane]));
            float d2 = wred32(fmaf(x0, a2ap[h * 64 + lane], x1 * a2ap[h * 64 + 32 + lane]));
            if (lane == 0) { g_x1ap[h * NA + n] = d1; g_x2ap[h * NA + n] = d2; }
        }
        float d3 = wred32(fmaf(x0, a2pa[lane], x1 * a2pa[32 + lane]));
        if (lane == 0) g_h1pa[n] = d3;
    } else {
        int n = gw - NA;
        float x0 = g_xp[(size_t)n * 64 + lane], x1 = g_xp[(size_t)n * 64 + 32 + lane];
        #pragma unroll
        for (int h = 0; h < 3; h++) {
            float d1 = wred32(fmaf(x0, a1pa[h * 64 + lane], x1 * a1pa[h * 64 + 32 + lane]));
            float d2 = wred32(fmaf(x0, a2pa[h * 64 + lane], x1 * a2pa[h * 64 + 32 + lane]));
            float d3 = wred32(fmaf(x0, a1pp[h * 64 + lane], x1 * a1pp[h * 64 + 32 + lane]));
            float d4 = wred32(fmaf(x0, a2pp[h * 64 + lane], x1 * a2pp[h * 64 + 32 + lane]));
            if (lane == 0) {
                g_x1pa[h * NP + n] = d1; g_x2pa[h * NP + n] = d2;
                g_x1pp[h * NP + n] = d3; g_x2pp[h * NP + n] = d4;
            }
        }
        float d5 = wred32(fmaf(x0, a2ap[lane], x1 * a2ap[32 + lane]));
        float d6 = wred32(fmaf(x0, a2pp[lane], x1 * a2pp[32 + lane]));
        if (lane == 0) { g_h1ap[n] = d5; g_h1pp[n] = d6; }
    }
}

// ---------------- edge aggregation (fp16 gathers, fp32 math) ----------------
__device__ __forceinline__ void relation_accum16(const int* __restrict__ rp,
                                                 const int* __restrict__ ts,
                                                 const __half2* __restrict__ h16,
                                                 const float* __restrict__ h1arr,
                                                 float x1, int n, int sub,
                                                 float4& acc, float& div) {
    int e = rp[n], end = rp[n + 1];
    #pragma unroll 4
    for (; e < end; ++e) {
        int t = __ldg(&ts[e]);
        float w = lrelu_exp(x1 + __ldg(&h1arr[t]));
        uint2 rv = *reinterpret_cast<const uint2*>(&h16[(size_t)t * 32 + (sub << 1)]);
        __half2 a = *reinterpret_cast<const __half2*>(&rv.x);
        __half2 bb = *reinterpret_cast<const __half2*>(&rv.y);
        float2 f0 = __half22float2(a);
        float2 f1 = __half22float2(bb);
        acc.x = fmaf(w, f0.x, acc.x);
        acc.y = fmaf(w, f0.y, acc.y);
        acc.z = fmaf(w, f1.x, acc.z);
        acc.w = fmaf(w, f1.y, acc.w);
        div += w;
    }
}

// hops 0 and 1: A + P aggregation, always writes mirrors + next-hop h1 scalars
__global__ void agg_kernel(int curA, int curP, int nxt, int h1cur, int h1nxt, int hop,
                           const float* __restrict__ a2pa_nx,
                           const float* __restrict__ a2ap_nx,
                           const float* __restrict__ a2pp_nx) {
    int lane = threadIdx.x & 31;
    int sub = lane & 15;
    int half = lane >> 4;
    if (blockIdx.x < BA_BLOCKS) {
        int warp = (blockIdx.x * blockDim.x + threadIdx.x) >> 5;
        int n = warp * 2 + half;
        const __half2* __restrict__ h = bufP16(curP);
        const float* __restrict__ h1 = g_h1ap + (size_t)h1cur * NP;
        float x1 = g_x1ap[hop * NA + n];
        float4 acc = {0.f, 0.f, 0.f, 0.f};
        float div = 0.f;
        relation_accum16(g_rp_ap, g_ts_ap, h, h1, x1, n, sub, acc, div);
        float w2 = lrelu_exp(x1 + g_x2ap[hop * NA + n]);
        const float4 xv = *reinterpret_cast<const float4*>(&g_xa[(size_t)n * 64 + (sub << 2)]);
        acc.x = fmaf(w2, xv.x, acc.x); acc.y = fmaf(w2, xv.y, acc.y);
        acc.z = fmaf(w2, xv.z, acc.z); acc.w = fmaf(w2, xv.w, acc.w);
        div += w2;
        float inv = 1.f / div;
        float4 r;
        r.x = eluf(acc.x * inv); r.y = eluf(acc.y * inv);
        r.z = eluf(acc.z * inv); r.w = eluf(acc.w * inv);
        uint2 st = pack_h4(r.x, r.y, r.z, r.w);
        *reinterpret_cast<uint2*>(&g_h16a[((size_t)nxt * NA + n) * 32 + (sub << 1)]) = st;
        const float4 va = *(const float4*)&a2pa_nx[sub << 2];
        float p = r.x * va.x + r.y * va.y + r.z * va.z + r.w * va.w;
        p = wred16(p);
        if (sub == 0) g_h1pa[(size_t)h1nxt * NA + n] = p;
    } else {
        int warp = ((blockIdx.x - BA_BLOCKS) * blockDim.x + threadIdx.x) >> 5;
        int n = warp * 2 + half;
        const __half2* __restrict__ hA = bufA16(curA);
        const __half2* __restrict__ hP = bufP16(curP);
        const float* __restrict__ h1a = g_h1pa + (size_t)h1cur * NA;
        const float* __restrict__ h1p = g_h1pp + (size_t)h1cur * NP;
        float x1a = g_x1pa[hop * NP + n];
        float x1p = g_x1pp[hop * NP + n];
        float4 acc1 = {0.f, 0.f, 0.f, 0.f}, acc2 = {0.f, 0.f, 0.f, 0.f};
        float div1 = 0.f, div2 = 0.f;
        relation_accum16(g_rp_pa, g_ts_pa, hA, h1a, x1a, n, sub, acc1, div1);
        relation_accum16(g_rp_pp, g_ts_pp, hP, h1p, x1p, n, sub, acc2, div2);
        const float4 xv = *reinterpret_cast<const float4*>(&g_xp[(size_t)n * 64 + (sub << 2)]);
        float w2a = lrelu_exp(x1a + g_x2pa[hop * NP + n]);
        float w2p = lrelu_exp(x1p + g_x2pp[hop * NP + n]);
        acc1.x = fmaf(w2a, xv.x, acc1.x); acc1.y = fmaf(w2a, xv.y, acc1.y);
        acc1.z = fmaf(w2a, xv.z, acc1.z); acc1.w = fmaf(w2a, xv.w, acc1.w);
        div1 += w2a;
        acc2.x = fmaf(w2p, xv.x, acc2.x); acc2.y = fmaf(w2p, xv.y, acc2.y);
        acc2.z = fmaf(w2p, xv.z, acc2.z); acc2.w = fmaf(w2p, xv.w, acc2.w);
        div2 += w2p;
        float i1 = 1.f / div1, i2 = 1.f / div2;
        float4 r;
        r.x = eluf(0.5f * (acc1.x * i1 + acc2.x * i2));
        r.y = eluf(0.5f * (acc1.y * i1 + acc2.y * i2));
        r.z = eluf(0.5f * (acc1.z * i1 + acc2.z * i2));
        r.w = eluf(0.5f * (acc1.w * i1 + acc2.w * i2));
        uint2 st = pack_h4(r.x, r.y, r.z, r.w);
        *reinterpret_cast<uint2*>(&g_h16p[((size_t)nxt * NP + n) * 32 + (sub << 1)]) = st;
        const float4 va = *(const float4*)&a2ap_nx[sub << 2];
        const float4 vp = *(const float4*)&a2pp_nx[sub << 2];
        float p1 = r.x * va.x + r.y * va.y + r.z * va.z + r.w * va.w;
        float p2 = r.x * vp.x + r.y * vp.y + r.z * vp.z + r.w * vp.w;
        p1 = wred16(p1);
        p2 = wred16(p2);
        if (sub == 0) {
            g_h1ap[(size_t)h1nxt * NP + n] = p1;
            g_h1pp[(size_t)h1nxt * NP + n] = p2;
        }
    }
}

// last hop: A-side aggregation only, with fc2 fused (h_p of last hop is dead)
__global__ void aggA_fc2_kernel(int curP, int h1cur,
                                const float* __restrict__ W,
                                const float* __restrict__ bias,
                                float* __restrict__ out) {
    __shared__ __align__(16) float wt[16 * 68];      // transposed W, padded stride
    __shared__ __align__(16) float rs[8][2][64];     // per-warp per-half h_a row
    int tid = threadIdx.x;
    // transpose W[k*16+j] -> wt[j*68+k]
    for (int idx = tid; idx < 1024; idx += 256) {
        int k = idx >> 4, j = idx & 15;
        wt[j * 68 + k] = W[idx];
    }
    __syncthreads();

    int lane = tid & 31, sub = lane & 15, half = lane >> 4;
    int w = tid >> 5;
    int warp = (blockIdx.x * blockDim.x + tid) >> 5;
    int n = warp * 2 + half;

    const __half2* __restrict__ h = bufP16(curP);
    const float* __restrict__ h1 = g_h1ap + (size_t)h1cur * NP;
    float x1 = g_x1ap[2 * NA + n];
    float4 acc = {0.f, 0.f, 0.f, 0.f};
    float div = 0.f;
    relation_accum16(g_rp_ap, g_ts_ap, h, h1, x1, n, sub, acc, div);
    float w2 = lrelu_exp(x1 + g_x2ap[2 * NA + n]);
    const float4 xv = *reinterpret_cast<const float4*>(&g_xa[(size_t)n * 64 + (sub << 2)]);
    acc.x = fmaf(w2, xv.x, acc.x); acc.y = fmaf(w2, xv.y, acc.y);
    acc.z = fmaf(w2, xv.z, acc.z); acc.w = fmaf(w2, xv.w, acc.w);
    div += w2;
    float inv = 1.f / div;
    float4 r;
    r.x = eluf(acc.x * inv); r.y = eluf(acc.y * inv);
    r.z = eluf(acc.z * inv); r.w = eluf(acc.w * inv);

    // stage h_a row in smem, then each lane computes output column `sub`
    *reinterpret_cast<float4*>(&rs[w][half][sub << 2]) = r;
    __syncwarp();
    float o = bias[sub];
    #pragma unroll
    for (int k4 = 0; k4 < 16; k4++) {
        float4 rv = *reinterpret_cast<const float4*>(&rs[w][half][k4 * 4]);
        float4 wv = *reinterpret_cast<const float4*>(&wt[sub * 68 + k4 * 4]);
        o += rv.x * wv.x + rv.y * wv.y + rv.z * wv.z + rv.w * wv.w;
    }
    out[(size_t)n * 16 + sub] = o;
}

// ---------------- launch ----------------
extern "C" void kernel_launch(void* const* d_in, const int* in_sizes, int n_in,
                              void* d_out, int out_size) {
    const float* x_a   = (const float*)d_in[0];
    const float* x_p   = (const float*)d_in[1];
    const int* ap_s    = (const int*)d_in[2];
    const int* ap_t    = (const int*)d_in[3];
    const int* pa_s    = (const int*)d_in[4];
    const int* pa_t    = (const int*)d_in[5];
    const int* pp_s    = (const int*)d_in[6];
    const int* pp_t    = (const int*)d_in[7];
    const float* fc1aw = (const float*)d_in[8];
    const float* fc1ab = (const float*)d_in[9];
    const float* fc1pw = (const float*)d_in[10];
    const float* fc1pb = (const float*)d_in[11];
    const float* fc2w  = (const float*)d_in[12];
    const float* fc2b  = (const float*)d_in[13];
    const float* a1ap  = (const float*)d_in[14];
    const float* a2ap  = (const float*)d_in[15];
    const float* a1pa  = (const float*)d_in[16];
    const float* a2pa  = (const float*)d_in[17];
    const float* a1pp  = (const float*)d_in[18];
    const float* a2pp  = (const float*)d_in[19];
    float* out = (float*)d_out;

    static cudaStream_t s2 = nullptr;
    static cudaEvent_t evF = nullptr, evJ = nullptr;
    if (s2 == nullptr) {
        cudaStreamCreateWithFlags(&s2, cudaStreamNonBlocking);
        cudaEventCreateWithFlags(&evF, cudaEventDisableTiming);
        cudaEventCreateWithFlags(&evJ, cudaEventDisableTiming);
    }

    // ---- fork: projection chain on s2, CSR chain on the main stream ----
    cudaEventRecord(evF, 0);
    cudaStreamWaitEvent(s2, evF, 0);

    proj_gemm2<<<GEMM_A_BLOCKS + GEMM_P_BLOCKS, 128, 0, s2>>>(x_a, fc1aw, fc1ab, x_p, fc1pw, fc1pb);
    sproj0_kernel<<<(NA + NP) / 8, 256, 0, s2>>>(a1ap, a2ap, a1pa, a2pa, a1pp, a2pp);
    cudaEventRecord(evJ, s2);

    // CSR build (main stream, overlapped)
    zero_cnt_kernel<<<977, 256>>>();
    hist_kernel<<<1024, 256>>>(ap_s, pa_s, pp_s);
    scan_passA<<<NBLK_SCAN, 256>>>();
    scan_passB<<<1, 96>>>();
    scan_passC<<<NBLK_SCAN, 256>>>();
    scatter_kernel<<<1500, 256>>>(ap_s, ap_t, pa_s, pa_t, pp_s, pp_t);

    // ---- join ----
    cudaStreamWaitEvent(0, evJ, 0);

    // hops 0 and 1 (full A+P), hop 2 (A only, fc2 fused)
    agg_kernel<<<BA_BLOCKS + BP_BLOCKS, 256>>>(2, 2, 0, 0, 1, 0,
                                               a2pa + 64, a2ap + 64, a2pp + 64);
    agg_kernel<<<BA_BLOCKS + BP_BLOCKS, 256>>>(0, 0, 1, 1, 0, 1,
                                               a2pa + 128, a2ap + 128, a2pp + 128);
    aggA_fc2_kernel<<<BA_BLOCKS, 256>>>(1, 0, fc2w, fc2b, out);
}

// round 10
// speedup vs baseline: 1.2362x; 1.0664x over previous
#include <cuda_runtime.h>
#include <cuda_fp16.h>
#include <cuda_bf16.h>
#include <math.h>

#define NA 50000
#define NP 100000
#define DA 512
#define DP 256
#define HID 64
#define NOUT 16
#define NE 2000000
#define CH 2048
#define NCH_A 25
#define NCH_P 49
#define NBLK_SCAN (NCH_A + 2*NCH_P)   // 123
#define BA_BLOCKS 3125   // NA/2 nodes -> 25000 warps
#define BP_BLOCKS 6250
#define GEMM_A_BLOCKS 391  // ceil(50000/128)
#define GEMM_P_BLOCKS 782  // ceil(100000/128)
#define AS_STRIDE 40       // halves per row in A-stage smem (conflict-free)

// ---------------- scratch ----------------
__device__ float g_xa[NA * HID];
__device__ float g_xp[NP * HID];
// fp16 gather mirrors; buffer index 2 == x mirror
__device__ __align__(16) __half2 g_h16a[3 * NA * 32];
__device__ __align__(16) __half2 g_h16p[3 * NP * 32];

__device__ int g_rp_ap[NA + 1];
__device__ int g_rp_pa[NP + 1];
__device__ int g_rp_pp[NP + 1];
__device__ int g_ts_ap[NE];
__device__ int g_ts_pa[NE];
__device__ int g_ts_pp[NE];
__device__ int g_cntA[NA];
__device__ int g_cntP1[NP];
__device__ int g_cntP2[NP];
__device__ int g_bsum[3 * 64];

// x-based attention scalars, all hops precomputed
__device__ float g_x1ap[3 * NA], g_x2ap[3 * NA];
__device__ float g_x1pa[3 * NP], g_x2pa[3 * NP], g_x1pp[3 * NP], g_x2pp[3 * NP];
// h-based scalars, double buffered
__device__ float g_h1pa[2 * NA];
__device__ float g_h1ap[2 * NP], g_h1pp[2 * NP];

// ---------------- helpers ----------------
__device__ __forceinline__ const __half2* bufA16(int c) { return g_h16a + (size_t)c * NA * 32; }
__device__ __forceinline__ const __half2* bufP16(int c) { return g_h16p + (size_t)c * NP * 32; }
__device__ __forceinline__ float eluf(float v) { return v > 0.f ? v : expm1f(v); }
__device__ __forceinline__ float lrelu_exp(float sc) {
    sc = sc >= 0.f ? sc : 0.2f * sc;
    return __expf(sc);
}
__device__ __forceinline__ float wred32(float v) {
    v += __shfl_down_sync(0xffffffffu, v, 16);
    v += __shfl_down_sync(0xffffffffu, v, 8);
    v += __shfl_down_sync(0xffffffffu, v, 4);
    v += __shfl_down_sync(0xffffffffu, v, 2);
    v += __shfl_down_sync(0xffffffffu, v, 1);
    return v;
}
__device__ __forceinline__ float wred16(float v) {
    v += __shfl_down_sync(0xffffffffu, v, 8, 16);
    v += __shfl_down_sync(0xffffffffu, v, 4, 16);
    v += __shfl_down_sync(0xffffffffu, v, 2, 16);
    v += __shfl_down_sync(0xffffffffu, v, 1, 16);
    return v;
}
__device__ __forceinline__ uint2 pack_h4(float x, float y, float z, float w) {
    __half2 q0 = __floats2half2_rn(x, y);
    __half2 q1 = __floats2half2_rn(z, w);
    uint2 st;
    st.x = *reinterpret_cast<unsigned*>(&q0);
    st.y = *reinterpret_cast<unsigned*>(&q1);
    return st;
}
__device__ __forceinline__ unsigned h2u(__half2 h) { return *reinterpret_cast<unsigned*>(&h); }
__device__ __forceinline__ void mma16816(float* d, unsigned a0, unsigned a1, unsigned a2, unsigned a3,
                                         unsigned b0, unsigned b1) {
    asm volatile(
        "mma.sync.aligned.m16n8k16.row.col.f32.f16.f16.f32 "
        "{%0,%1,%2,%3}, {%4,%5,%6,%7}, {%8,%9}, {%0,%1,%2,%3};"
        : "+f"(d[0]), "+f"(d[1]), "+f"(d[2]), "+f"(d[3])
        : "r"(a0), "r"(a1), "r"(a2), "r"(a3), "r"(b0), "r"(b1));
}

// ---------------- CSR build ----------------
__global__ void zero_cnt_kernel() {
    int i = blockIdx.x * blockDim.x + threadIdx.x;
    int stride = gridDim.x * blockDim.x;
    for (; i < NA + 2 * NP; i += stride) {
        if (i < NA) g_cntA[i] = 0;
        else if (i < NA + NP) g_cntP1[i - NA] = 0;
        else g_cntP2[i - NA - NP] = 0;
    }
}

__global__ void hist_kernel(const int* __restrict__ ap_s,
                            const int* __restrict__ pa_s,
                            const int* __restrict__ pp_s) {
    const int Q = NE / 4;
    int i = blockIdx.x * blockDim.x + threadIdx.x;
    int stride = gridDim.x * blockDim.x;
    for (; i < 3 * Q; i += stride) {
        int4 v;
        int* cnt;
        if (i < Q)          { v = ((const int4*)ap_s)[i];        cnt = g_cntA;  }
        else if (i < 2 * Q) { v = ((const int4*)pa_s)[i - Q];    cnt = g_cntP1; }
        else                { v = ((const int4*)pp_s)[i - 2 * Q]; cnt = g_cntP2; }
        atomicAdd(&cnt[v.x], 1);
        atomicAdd(&cnt[v.y], 1);
        atomicAdd(&cnt[v.z], 1);
        atomicAdd(&cnt[v.w], 1);
    }
}

__device__ __forceinline__ void rel_of(int b, int& rel, int& chunk) {
    if (b < NCH_A)              { rel = 0; chunk = b; }
    else if (b < NCH_A + NCH_P) { rel = 1; chunk = b - NCH_A; }
    else                        { rel = 2; chunk = b - NCH_A - NCH_P; }
}

__global__ void scan_passA() {
    int rel, chunk; rel_of(blockIdx.x, rel, chunk);
    const int* cnt = rel == 0 ? g_cntA : (rel == 1 ? g_cntP1 : g_cntP2);
    int n = rel == 0 ? NA : NP;
    int base = chunk * CH;
    int s = 0;
    #pragma unroll
    for (int j = 0; j < 8; j++) {
        int i = base + threadIdx.x + 256 * j;
        if (i < n) s += cnt[i];
    }
    #pragma unroll
    for (int o = 16; o; o >>= 1) s += __shfl_down_sync(0xffffffffu, s, o);
    __shared__ int sh[8];
    int lane = threadIdx.x & 31, wid = threadIdx.x >> 5;
    if (lane == 0) sh[wid] = s;
    __syncthreads();
    if (wid == 0) {
        int t = (lane < 8) ? sh[lane] : 0;
        #pragma unroll
        for (int o = 4; o; o >>= 1) t += __shfl_down_sync(0xffffffffu, t, o);
        if (lane == 0) g_bsum[rel * 64 + chunk] = t;
    }
}

__global__ void scan_passB() {   // 1 block, 96 threads
    int wid = threadIdx.x >> 5, lane = threadIdx.x & 31;
    if (wid < 3) {
        int nch = (wid == 0) ? NCH_A : NCH_P;
        int carry = 0;
        #pragma unroll
        for (int c0 = 0; c0 < 64; c0 += 32) {
            int idx = c0 + lane;
            int v = (idx < nch) ? g_bsum[wid * 64 + idx] : 0;
            int x = v;
            #pragma unroll
            for (int o = 1; o < 32; o <<= 1) {
                int y = __shfl_up_sync(0xffffffffu, x, o);
                if (lane >= o) x += y;
            }
            g_bsum[wid * 64 + idx] = carry + x - v;   // exclusive
            carry += __shfl_sync(0xffffffffu, x, 31);
        }
        if (lane == 0) {
            if (wid == 0)      g_rp_ap[NA] = carry;
            else if (wid == 1) g_rp_pa[NP] = carry;
            else               g_rp_pp[NP] = carry;
        }
    }
}

__global__ void scan_passC() {   // re-scan chunk, write rp, zero cnt
    int rel, chunk; rel_of(blockIdx.x, rel, chunk);
    int* cnt; int* rp; int n;
    if (rel == 0)      { cnt = g_cntA;  rp = g_rp_ap; n = NA; }
    else if (rel == 1) { cnt = g_cntP1; rp = g_rp_pa; n = NP; }
    else               { cnt = g_cntP2; rp = g_rp_pp; n = NP; }
    int tid = threadIdx.x, lane = tid & 31, wid = tid >> 5;
    int i0 = chunk * CH + tid * 8;
    int v[8];
    #pragma unroll
    for (int j = 0; j < 8; j++) v[j] = (i0 + j < n) ? cnt[i0 + j] : 0;
    int s = 0;
    #pragma unroll
    for (int j = 0; j < 8; j++) { int t = v[j]; v[j] = s; s += t; }
    int x = s;
    #pragma unroll
    for (int o = 1; o < 32; o <<= 1) {
        int y = __shfl_up_sync(0xffffffffu, x, o);
        if (lane >= o) x += y;
    }
    __shared__ int wsum[8];
    if (lane == 31) wsum[wid] = x;
    __syncthreads();
    if (wid == 0 && lane < 8) {
        int t = wsum[lane];
        int xx = t;
        #pragma unroll
        for (int o = 1; o < 8; o <<= 1) {
            int y = __shfl_up_sync(0xffu, xx, o);
            if (lane >= o) xx += y;
        }
        wsum[lane] = xx - t;
    }
    __syncthreads();
    int off = g_bsum[rel * 64 + chunk] + wsum[wid] + (x - s);
    #pragma unroll
    for (int j = 0; j < 8; j++) {
        int i = i0 + j;
        if (i < n) { rp[i] = off + v[j]; cnt[i] = 0; }
    }
}

__global__ void scatter_kernel(const int* __restrict__ ap_s, const int* __restrict__ ap_t,
                               const int* __restrict__ pa_s, const int* __restrict__ pa_t,
                               const int* __restrict__ pp_s, const int* __restrict__ pp_t) {
    const int Q = NE / 4;
    int i = blockIdx.x * blockDim.x + threadIdx.x;
    int stride = gridDim.x * blockDim.x;
    for (; i < 3 * Q; i += stride) {
        int4 sv, tv;
        int* cnt; const int* rp; int* ts;
        if (i < Q) {
            sv = ((const int4*)ap_s)[i]; tv = ((const int4*)ap_t)[i];
            cnt = g_cntA; rp = g_rp_ap; ts = g_ts_ap;
        } else if (i < 2 * Q) {
            sv = ((const int4*)pa_s)[i - Q]; tv = ((const int4*)pa_t)[i - Q];
            cnt = g_cntP1; rp = g_rp_pa; ts = g_ts_pa;
        } else {
            sv = ((const int4*)pp_s)[i - 2 * Q]; tv = ((const int4*)pp_t)[i - 2 * Q];
            cnt = g_cntP2; rp = g_rp_pp; ts = g_ts_pp;
        }
        int p0 = rp[sv.x] + atomicAdd(&cnt[sv.x], 1); ts[p0] = tv.x;
        int p1 = rp[sv.y] + atomicAdd(&cnt[sv.y], 1); ts[p1] = tv.y;
        int p2 = rp[sv.z] + atomicAdd(&cnt[sv.z], 1); ts[p2] = tv.z;
        int p3 = rp[sv.w] + atomicAdd(&cnt[sv.w], 1); ts[p3] = tv.w;
    }
}

// ---------------- projection GEMM via fp16 tensor cores (mma.sync m16n8k16) ----
// 256 threads, tile 128 nodes x 64 cols. Warp w covers rows 16w..16w+15.
// A staged fp32->fp16 in smem [128][AS_STRIDE]; W staged transposed as half2(k,k+1) pairs.
__global__ __launch_bounds__(256) void proj_mma(
    const float* __restrict__ XA, const float* __restrict__ WA, const float* __restrict__ bA,
    const float* __restrict__ XP, const float* __restrict__ WP, const float* __restrict__ bP) {
    __shared__ __align__(16) __half as_[128 * AS_STRIDE];
    __shared__ __align__(16) __half2 bs[64 * 20];   // [n][k/2], K-chunk = 32

    int b = blockIdx.x;
    const float* X; const float* W; const float* bias; float* Y; __half2* Y16; int N, K, nb;
    if (b < GEMM_A_BLOCKS) {
        X = XA; W = WA; bias = bA; Y = g_xa; N = NA; K = DA; nb = b * 128;
        Y16 = g_h16a + (size_t)2 * NA * 32;
    } else {
        b -= GEMM_A_BLOCKS;
        X = XP; W = WP; bias = bP; Y = g_xp; N = NP; K = DP; nb = b * 128;
        Y16 = g_h16p + (size_t)2 * NP * 32;
    }

    int tid = threadIdx.x;
    int lane = tid & 31, w = tid >> 5;

    float acc[8][4];
    #pragma unroll
    for (int nt = 0; nt < 8; nt++)
        #pragma unroll
        for (int q = 0; q < 4; q++) acc[nt][q] = 0.f;

    for (int kc = 0; kc < K; kc += 32) {
        // stage X: thread -> row tid>>1, halves (tid&1)*16 .. +15
        {
            int row = tid >> 1, kb16 = (tid & 1) * 16;
            int gn = nb + row;
            #pragma unroll
            for (int q = 0; q < 4; q++) {
                float4 v = (gn < N) ? *(const float4*)&X[(size_t)gn * K + kc + kb16 + q * 4]
                                    : make_float4(0.f, 0.f, 0.f, 0.f);
                uint2 st;
                st.x = h2u(__floats2half2_rn(v.x, v.y));
                st.y = h2u(__floats2half2_rn(v.z, v.w));
                *reinterpret_cast<uint2*>(&as_[row * AS_STRIDE + kb16 + q * 4]) = st;
            }
        }
        // stage W transposed: bs[n][k/2] = half2(W[k][n], W[k+1][n])
        {
            int n = tid & 63, kk0 = (tid >> 6) * 2;
            #pragma unroll
            for (int it = 0; it < 4; it++) {
                int kk = kk0 + it * 8;
                float w0 = W[(size_t)(kc + kk) * 64 + n];
                float w1 = W[(size_t)(kc + kk + 1) * 64 + n];
                bs[n * 20 + (kk >> 1)] = __floats2half2_rn(w0, w1);
            }
        }
        __syncthreads();
        int g = lane >> 2, q2 = (lane & 3) * 2;
        #pragma unroll
        for (int ks = 0; ks < 2; ks++) {
            int kb = ks * 16;
            const __half* ar0 = &as_[(16 * w + g) * AS_STRIDE + kb + q2];
            const __half* ar1 = &as_[(16 * w + g + 8) * AS_STRIDE + kb + q2];
            unsigned a0 = *reinterpret_cast<const unsigned*>(ar0);
            unsigned a2 = *reinterpret_cast<const unsigned*>(ar0 + 8);
            unsigned a1 = *reinterpret_cast<const unsigned*>(ar1);
            unsigned a3 = *reinterpret_cast<const unsigned*>(ar1 + 8);
            #pragma unroll
            for (int nt = 0; nt < 8; nt++) {
                int n = nt * 8 + (lane >> 2);
                unsigned b0 = h2u(bs[n * 20 + (kb >> 1) + (lane & 3)]);
                unsigned b1 = h2u(bs[n * 20 + (kb >> 1) + (lane & 3) + 4]);
                mma16816(acc[nt], a0, a1, a2, a3, b0, b1);
            }
        }
        __syncthreads();
    }

    // epilogue: bias + relu, write fp32 Y and fp16 mirror
    int g = lane >> 2, q2 = (lane & 3) * 2;
    int row0 = nb + 16 * w + g, row1 = row0 + 8;
    #pragma unroll
    for (int nt = 0; nt < 8; nt++) {
        int col = nt * 8 + q2;
        float b0v = __ldg(&bias[col]), b1v = __ldg(&bias[col + 1]);
        if (row0 < N) {
            float y0 = fmaxf(acc[nt][0] + b0v, 0.f);
            float y1 = fmaxf(acc[nt][1] + b1v, 0.f);
            float2 f2 = {y0, y1};
            *reinterpret_cast<float2*>(&Y[(size_t)row0 * 64 + col]) = f2;
            *reinterpret_cast<unsigned*>(&Y16[(size_t)row0 * 32 + (col >> 1)]) =
                h2u(__floats2half2_rn(y0, y1));
        }
        if (row1 < N) {
            float y0 = fmaxf(acc[nt][2] + b0v, 0.f);
            float y1 = fmaxf(acc[nt][3] + b1v, 0.f);
            float2 f2 = {y0, y1};
            *reinterpret_cast<float2*>(&Y[(size_t)row1 * 64 + col]) = f2;
            *reinterpret_cast<unsigned*>(&Y16[(size_t)row1 * 32 + (col >> 1)]) =
                h2u(__floats2half2_rn(y0, y1));
        }
    }
}

// ---------------- upfront scalar projections ----------------
__global__ void sproj0_kernel(const float* __restrict__ a1ap, const float* __restrict__ a2ap,
                              const float* __restrict__ a1pa, const float* __restrict__ a2pa,
                              const float* __restrict__ a1pp, const float* __restrict__ a2pp) {
    int gw = (blockIdx.x * blockDim.x + threadIdx.x) >> 5;
    int lane = threadIdx.x & 31;
    if (gw < NA) {
        int n = gw;
        float x0 = g_xa[(size_t)n * 64 + lane], x1 = g_xa[(size_t)n * 64 + 32 + lane];
        #pragma unroll
        for (int h = 0; h < 3; h++) {
            float d1 = wred32(fmaf(x0, a1ap[h * 64 + lane], x1 * a1ap[h * 64 + 32 + lane]));
            float d2 = wred32(fmaf(x0, a2ap[h * 64 + lane], x1 * a2ap[h * 64 + 32 + lane]));
            if (lane == 0) { g_x1ap[h * NA + n] = d1; g_x2ap[h * NA + n] = d2; }
        }
        float d3 = wred32(fmaf(x0, a2pa[lane], x1 * a2pa[32 + lane]));
        if (lane == 0) g_h1pa[n] = d3;
    } else {
        int n = gw - NA;
        float x0 = g_xp[(size_t)n * 64 + lane], x1 = g_xp[(size_t)n * 64 + 32 + lane];
        #pragma unroll
        for (int h = 0; h < 3; h++) {
            float d1 = wred32(fmaf(x0, a1pa[h * 64 + lane], x1 * a1pa[h * 64 + 32 + lane]));
            float d2 = wred32(fmaf(x0, a2pa[h * 64 + lane], x1 * a2pa[h * 64 + 32 + lane]));
            float d3 = wred32(fmaf(x0, a1pp[h * 64 + lane], x1 * a1pp[h * 64 + 32 + lane]));
            float d4 = wred32(fmaf(x0, a2pp[h * 64 + lane], x1 * a2pp[h * 64 + 32 + lane]));
            if (lane == 0) {
                g_x1pa[h * NP + n] = d1; g_x2pa[h * NP + n] = d2;
                g_x1pp[h * NP + n] = d3; g_x2pp[h * NP + n] = d4;
            }
        }
        float d5 = wred32(fmaf(x0, a2ap[lane], x1 * a2ap[32 + lane]));
        float d6 = wred32(fmaf(x0, a2pp[lane], x1 * a2pp[32 + lane]));
        if (lane == 0) { g_h1ap[n] = d5; g_h1pp[n] = d6; }
    }
}

// ---------------- edge aggregation (fp16 gathers, fp32 math) ----------------
__device__ __forceinline__ void relation_accum16(const int* __restrict__ rp,
                                                 const int* __restrict__ ts,
                                                 const __half2* __restrict__ h16,
                                                 const float* __restrict__ h1arr,
                                                 float x1, int n, int sub,
                                                 float4& acc, float& div) {
    int e = rp[n], end = rp[n + 1];
    #pragma unroll 4
    for (; e < end; ++e) {
        int t = __ldg(&ts[e]);
        float w = lrelu_exp(x1 + __ldg(&h1arr[t]));
        uint2 rv = *reinterpret_cast<const uint2*>(&h16[(size_t)t * 32 + (sub << 1)]);
        __half2 a = *reinterpret_cast<const __half2*>(&rv.x);
        __half2 bb = *reinterpret_cast<const __half2*>(&rv.y);
        float2 f0 = __half22float2(a);
        float2 f1 = __half22float2(bb);
        acc.x = fmaf(w, f0.x, acc.x);
        acc.y = fmaf(w, f0.y, acc.y);
        acc.z = fmaf(w, f1.x, acc.z);
        acc.w = fmaf(w, f1.y, acc.w);
        div += w;
    }
}

// hops 0 and 1: A + P aggregation, always writes mirrors + next-hop h1 scalars
__global__ void agg_kernel(int curA, int curP, int nxt, int h1cur, int h1nxt, int hop,
                           const float* __restrict__ a2pa_nx,
                           const float* __restrict__ a2ap_nx,
                           const float* __restrict__ a2pp_nx) {
    int lane = threadIdx.x & 31;
    int sub = lane & 15;
    int half = lane >> 4;
    if (blockIdx.x < BA_BLOCKS) {
        int warp = (blockIdx.x * blockDim.x + threadIdx.x) >> 5;
        int n = warp * 2 + half;
        const __half2* __restrict__ h = bufP16(curP);
        const float* __restrict__ h1 = g_h1ap + (size_t)h1cur * NP;
        float x1 = g_x1ap[hop * NA + n];
        float4 acc = {0.f, 0.f, 0.f, 0.f};
        float div = 0.f;
        relation_accum16(g_rp_ap, g_ts_ap, h, h1, x1, n, sub, acc, div);
        float w2 = lrelu_exp(x1 + g_x2ap[hop * NA + n]);
        const float4 xv = *reinterpret_cast<const float4*>(&g_xa[(size_t)n * 64 + (sub << 2)]);
        acc.x = fmaf(w2, xv.x, acc.x); acc.y = fmaf(w2, xv.y, acc.y);
        acc.z = fmaf(w2, xv.z, acc.z); acc.w = fmaf(w2, xv.w, acc.w);
        div += w2;
        float inv = 1.f / div;
        float4 r;
        r.x = eluf(acc.x * inv); r.y = eluf(acc.y * inv);
        r.z = eluf(acc.z * inv); r.w = eluf(acc.w * inv);
        uint2 st = pack_h4(r.x, r.y, r.z, r.w);
        *reinterpret_cast<uint2*>(&g_h16a[((size_t)nxt * NA + n) * 32 + (sub << 1)]) = st;
        const float4 va = *(const float4*)&a2pa_nx[sub << 2];
        float p = r.x * va.x + r.y * va.y + r.z * va.z + r.w * va.w;
        p = wred16(p);
        if (sub == 0) g_h1pa[(size_t)h1nxt * NA + n] = p;
    } else {
        int warp = ((blockIdx.x - BA_BLOCKS) * blockDim.x + threadIdx.x) >> 5;
        int n = warp * 2 + half;
        const __half2* __restrict__ hA = bufA16(curA);
        const __half2* __restrict__ hP = bufP16(curP);
        const float* __restrict__ h1a = g_h1pa + (size_t)h1cur * NA;
        const float* __restrict__ h1p = g_h1pp + (size_t)h1cur * NP;
        float x1a = g_x1pa[hop * NP + n];
        float x1p = g_x1pp[hop * NP + n];
        float4 acc1 = {0.f, 0.f, 0.f, 0.f}, acc2 = {0.f, 0.f, 0.f, 0.f};
        float div1 = 0.f, div2 = 0.f;
        relation_accum16(g_rp_pa, g_ts_pa, hA, h1a, x1a, n, sub, acc1, div1);
        relation_accum16(g_rp_pp, g_ts_pp, hP, h1p, x1p, n, sub, acc2, div2);
        const float4 xv = *reinterpret_cast<const float4*>(&g_xp[(size_t)n * 64 + (sub << 2)]);
        float w2a = lrelu_exp(x1a + g_x2pa[hop * NP + n]);
        float w2p = lrelu_exp(x1p + g_x2pp[hop * NP + n]);
        acc1.x = fmaf(w2a, xv.x, acc1.x); acc1.y = fmaf(w2a, xv.y, acc1.y);
        acc1.z = fmaf(w2a, xv.z, acc1.z); acc1.w = fmaf(w2a, xv.w, acc1.w);
        div1 += w2a;
        acc2.x = fmaf(w2p, xv.x, acc2.x); acc2.y = fmaf(w2p, xv.y, acc2.y);
        acc2.z = fmaf(w2p, xv.z, acc2.z); acc2.w = fmaf(w2p, xv.w, acc2.w);
        div2 += w2p;
        float i1 = 1.f / div1, i2 = 1.f / div2;
        float4 r;
        r.x = eluf(0.5f * (acc1.x * i1 + acc2.x * i2));
        r.y = eluf(0.5f * (acc1.y * i1 + acc2.y * i2));
        r.z = eluf(0.5f * (acc1.z * i1 + acc2.z * i2));
        r.w = eluf(0.5f * (acc1.w * i1 + acc2.w * i2));
        uint2 st = pack_h4(r.x, r.y, r.z, r.w);
        *reinterpret_cast<uint2*>(&g_h16p[((size_t)nxt * NP + n) * 32 + (sub << 1)]) = st;
        const float4 va = *(const float4*)&a2ap_nx[sub << 2];
        const float4 vp = *(const float4*)&a2pp_nx[sub << 2];
        float p1 = r.x * va.x + r.y * va.y + r.z * va.z + r.w * va.w;
        float p2 = r.x * vp.x + r.y * vp.y + r.z * vp.z + r.w * vp.w;
        p1 = wred16(p1);
        p2 = wred16(p2);
        if (sub == 0) {
            g_h1ap[(size_t)h1nxt * NP + n] = p1;
            g_h1pp[(size_t)h1nxt * NP + n] = p2;
        }
    }
}

// last hop: A-side aggregation only, with fc2 fused (h_p of last hop is dead)
__global__ void aggA_fc2_kernel(int curP, int h1cur,
                                const float* __restrict__ W,
                                const float* __restrict__ bias,
                                float* __restrict__ out) {
    __shared__ __align__(16) float wt[16 * 68];      // transposed W, padded stride
    __shared__ __align__(16) float rs[8][2][64];     // per-warp per-half h_a row
    int tid = threadIdx.x;
    for (int idx = tid; idx < 1024; idx += 256) {
        int k = idx >> 4, j = idx & 15;
        wt[j * 68 + k] = W[idx];
    }
    __syncthreads();

    int lane = tid & 31, sub = lane & 15, half = lane >> 4;
    int w = tid >> 5;
    int warp = (blockIdx.x * blockDim.x + tid) >> 5;
    int n = warp * 2 + half;

    const __half2* __restrict__ h = bufP16(curP);
    const float* __restrict__ h1 = g_h1ap + (size_t)h1cur * NP;
    float x1 = g_x1ap[2 * NA + n];
    float4 acc = {0.f, 0.f, 0.f, 0.f};
    float div = 0.f;
    relation_accum16(g_rp_ap, g_ts_ap, h, h1, x1, n, sub, acc, div);
    float w2 = lrelu_exp(x1 + g_x2ap[2 * NA + n]);
    const float4 xv = *reinterpret_cast<const float4*>(&g_xa[(size_t)n * 64 + (sub << 2)]);
    acc.x = fmaf(w2, xv.x, acc.x); acc.y = fmaf(w2, xv.y, acc.y);
    acc.z = fmaf(w2, xv.z, acc.z); acc.w = fmaf(w2, xv.w, acc.w);
    div += w2;
    float inv = 1.f / div;
    float4 r;
    r.x = eluf(acc.x * inv); r.y = eluf(acc.y * inv);
    r.z = eluf(acc.z * inv); r.w = eluf(acc.w * inv);

    *reinterpret_cast<float4*>(&rs[w][half][sub << 2]) = r;
    __syncwarp();
    float o = bias[sub];
    #pragma unroll
    for (int k4 = 0; k4 < 16; k4++) {
        float4 rv = *reinterpret_cast<const float4*>(&rs[w][half][k4 * 4]);
        float4 wv = *reinterpret_cast<const float4*>(&wt[sub * 68 + k4 * 4]);
        o += rv.x * wv.x + rv.y * wv.y + rv.z * wv.z + rv.w * wv.w;
    }
    out[(size_t)n * 16 + sub] = o;
}

// ---------------- launch ----------------
extern "C" void kernel_launch(void* const* d_in, const int* in_sizes, int n_in,
                              void* d_out, int out_size) {
    const float* x_a   = (const float*)d_in[0];
    const float* x_p   = (const float*)d_in[1];
    const int* ap_s    = (const int*)d_in[2];
    const int* ap_t    = (const int*)d_in[3];
    const int* pa_s    = (const int*)d_in[4];
    const int* pa_t    = (const int*)d_in[5];
    const int* pp_s    = (const int*)d_in[6];
    const int* pp_t    = (const int*)d_in[7];
    const float* fc1aw = (const float*)d_in[8];
    const float* fc1ab = (const float*)d_in[9];
    const float* fc1pw = (const float*)d_in[10];
    const float* fc1pb = (const float*)d_in[11];
    const float* fc2w  = (const float*)d_in[12];
    const float* fc2b  = (const float*)d_in[13];
    const float* a1ap  = (const float*)d_in[14];
    const float* a2ap  = (const float*)d_in[15];
    const float* a1pa  = (const float*)d_in[16];
    const float* a2pa  = (const float*)d_in[17];
    const float* a1pp  = (const float*)d_in[18];
    const float* a2pp  = (const float*)d_in[19];
    float* out = (float*)d_out;

    static cudaStream_t s2 = nullptr;
    static cudaEvent_t evF = nullptr, evJ = nullptr;
    if (s2 == nullptr) {
        cudaStreamCreateWithFlags(&s2, cudaStreamNonBlocking);
        cudaEventCreateWithFlags(&evF, cudaEventDisableTiming);
        cudaEventCreateWithFlags(&evJ, cudaEventDisableTiming);
    }

    // ---- fork: projection chain on s2, CSR chain on the main stream ----
    cudaEventRecord(evF, 0);
    cudaStreamWaitEvent(s2, evF, 0);

    proj_mma<<<GEMM_A_BLOCKS + GEMM_P_BLOCKS, 256, 0, s2>>>(x_a, fc1aw, fc1ab, x_p, fc1pw, fc1pb);
    sproj0_kernel<<<(NA + NP) / 8, 256, 0, s2>>>(a1ap, a2ap, a1pa, a2pa, a1pp, a2pp);
    cudaEventRecord(evJ, s2);

    // CSR build (main stream, overlapped)
    zero_cnt_kernel<<<977, 256>>>();
    hist_kernel<<<1024, 256>>>(ap_s, pa_s, pp_s);
    scan_passA<<<NBLK_SCAN, 256>>>();
    scan_passB<<<1, 96>>>();
    scan_passC<<<NBLK_SCAN, 256>>>();
    scatter_kernel<<<1500, 256>>>(ap_s, ap_t, pa_s, pa_t, pp_s, pp_t);

    // ---- join ----
    cudaStreamWaitEvent(0, evJ, 0);

    // hops 0 and 1 (full A+P), hop 2 (A only, fc2 fused)
    agg_kernel<<<BA_BLOCKS + BP_BLOCKS, 256>>>(2, 2, 0, 0, 1, 0,
                                               a2pa + 64, a2ap + 64, a2pp + 64);
    agg_kernel<<<BA_BLOCKS + BP_BLOCKS, 256>>>(0, 0, 1, 1, 0, 1,
                                               a2pa + 128, a2ap + 128, a2pp + 128);
    aggA_fc2_kernel<<<BA_BLOCKS, 256>>>(1, 0, fc2w, fc2b, out);
}

// round 11
// speedup vs baseline: 1.3479x; 1.0903x over previous
#include <cuda_runtime.h>
#include <cuda_fp16.h>
#include <cuda_bf16.h>
#include <math.h>

#define NA 50000
#define NP 100000
#define DA 512
#define DP 256
#define HID 64
#define NOUT 16
#define NE 2000000
#define CH 2048
#define NCH_A 25
#define NCH_P 49
#define NBLK_SCAN (NCH_A + 2*NCH_P)   // 123
#define BA_BLOCKS 3125   // NA/2 nodes -> 25000 warps
#define BP_BLOCKS 6250
#define GEMM_A_BLOCKS 391  // ceil(50000/128)
#define GEMM_P_BLOCKS 782  // ceil(100000/128)
#define AS_STRIDE 40       // halves per row in A-stage smem (conflict-free)

// ---------------- scratch ----------------
__device__ float g_xa[NA * HID];
__device__ float g_xp[NP * HID];
// fp16 gather mirrors; buffer index 2 == x mirror
__device__ __align__(16) __half2 g_h16a[3 * NA * 32];
__device__ __align__(16) __half2 g_h16p[3 * NP * 32];

__device__ int g_rp_ap[NA + 1];
__device__ int g_rp_pa[NP + 1];
__device__ int g_rp_pp[NP + 1];
__device__ int g_ts_ap[NE];
__device__ int g_ts_pa[NE];
__device__ int g_ts_pp[NE];
__device__ int g_cntA[NA];
__device__ int g_cntP1[NP];
__device__ int g_cntP2[NP];
__device__ int g_bsum[3 * 64];

// x-based attention scalars, all hops precomputed
__device__ float g_x1ap[3 * NA], g_x2ap[3 * NA];
__device__ float g_x1pa[3 * NP], g_x2pa[3 * NP], g_x1pp[3 * NP], g_x2pp[3 * NP];
// h-based scalars, double buffered
__device__ float g_h1pa[2 * NA];
__device__ float g_h1ap[2 * NP], g_h1pp[2 * NP];

// ---------------- helpers ----------------
__device__ __forceinline__ const __half2* bufA16(int c) { return g_h16a + (size_t)c * NA * 32; }
__device__ __forceinline__ const __half2* bufP16(int c) { return g_h16p + (size_t)c * NP * 32; }
__device__ __forceinline__ float eluf(float v) { return v > 0.f ? v : expm1f(v); }
__device__ __forceinline__ float lrelu_exp(float sc) {
    sc = sc >= 0.f ? sc : 0.2f * sc;
    return __expf(sc);
}
__device__ __forceinline__ float wred32(float v) {
    v += __shfl_down_sync(0xffffffffu, v, 16);
    v += __shfl_down_sync(0xffffffffu, v, 8);
    v += __shfl_down_sync(0xffffffffu, v, 4);
    v += __shfl_down_sync(0xffffffffu, v, 2);
    v += __shfl_down_sync(0xffffffffu, v, 1);
    return v;
}
__device__ __forceinline__ float wred8(float v) {
    v += __shfl_down_sync(0xffffffffu, v, 4, 8);
    v += __shfl_down_sync(0xffffffffu, v, 2, 8);
    v += __shfl_down_sync(0xffffffffu, v, 1, 8);
    return v;
}
__device__ __forceinline__ unsigned h2u(__half2 h) { return *reinterpret_cast<unsigned*>(&h); }
__device__ __forceinline__ void mma16816(float* d, unsigned a0, unsigned a1, unsigned a2, unsigned a3,
                                         unsigned b0, unsigned b1) {
    asm volatile(
        "mma.sync.aligned.m16n8k16.row.col.f32.f16.f16.f32 "
        "{%0,%1,%2,%3}, {%4,%5,%6,%7}, {%8,%9}, {%0,%1,%2,%3};"
        : "+f"(d[0]), "+f"(d[1]), "+f"(d[2]), "+f"(d[3])
        : "r"(a0), "r"(a1), "r"(a2), "r"(a3), "r"(b0), "r"(b1));
}

// ---------------- CSR build ----------------
__global__ void zero_cnt_kernel() {
    int i = blockIdx.x * blockDim.x + threadIdx.x;
    int stride = gridDim.x * blockDim.x;
    for (; i < NA + 2 * NP; i += stride) {
        if (i < NA) g_cntA[i] = 0;
        else if (i < NA + NP) g_cntP1[i - NA] = 0;
        else g_cntP2[i - NA - NP] = 0;
    }
}

__global__ void hist_kernel(const int* __restrict__ ap_s,
                            const int* __restrict__ pa_s,
                            const int* __restrict__ pp_s) {
    const int Q = NE / 4;
    int i = blockIdx.x * blockDim.x + threadIdx.x;
    int stride = gridDim.x * blockDim.x;
    for (; i < 3 * Q; i += stride) {
        int4 v;
        int* cnt;
        if (i < Q)          { v = ((const int4*)ap_s)[i];        cnt = g_cntA;  }
        else if (i < 2 * Q) { v = ((const int4*)pa_s)[i - Q];    cnt = g_cntP1; }
        else                { v = ((const int4*)pp_s)[i - 2 * Q]; cnt = g_cntP2; }
        atomicAdd(&cnt[v.x], 1);
        atomicAdd(&cnt[v.y], 1);
        atomicAdd(&cnt[v.z], 1);
        atomicAdd(&cnt[v.w], 1);
    }
}

__device__ __forceinline__ void rel_of(int b, int& rel, int& chunk) {
    if (b < NCH_A)              { rel = 0; chunk = b; }
    else if (b < NCH_A + NCH_P) { rel = 1; chunk = b - NCH_A; }
    else                        { rel = 2; chunk = b - NCH_A - NCH_P; }
}

__global__ void scan_passA() {
    int rel, chunk; rel_of(blockIdx.x, rel, chunk);
    const int* cnt = rel == 0 ? g_cntA : (rel == 1 ? g_cntP1 : g_cntP2);
    int n = rel == 0 ? NA : NP;
    int base = chunk * CH;
    int s = 0;
    #pragma unroll
    for (int j = 0; j < 8; j++) {
        int i = base + threadIdx.x + 256 * j;
        if (i < n) s += cnt[i];
    }
    #pragma unroll
    for (int o = 16; o; o >>= 1) s += __shfl_down_sync(0xffffffffu, s, o);
    __shared__ int sh[8];
    int lane = threadIdx.x & 31, wid = threadIdx.x >> 5;
    if (lane == 0) sh[wid] = s;
    __syncthreads();
    if (wid == 0) {
        int t = (lane < 8) ? sh[lane] : 0;
        #pragma unroll
        for (int o = 4; o; o >>= 1) t += __shfl_down_sync(0xffffffffu, t, o);
        if (lane == 0) g_bsum[rel * 64 + chunk] = t;
    }
}

__global__ void scan_passB() {   // 1 block, 96 threads
    int wid = threadIdx.x >> 5, lane = threadIdx.x & 31;
    if (wid < 3) {
        int nch = (wid == 0) ? NCH_A : NCH_P;
        int carry = 0;
        #pragma unroll
        for (int c0 = 0; c0 < 64; c0 += 32) {
            int idx = c0 + lane;
            int v = (idx < nch) ? g_bsum[wid * 64 + idx] : 0;
            int x = v;
            #pragma unroll
            for (int o = 1; o < 32; o <<= 1) {
                int y = __shfl_up_sync(0xffffffffu, x, o);
                if (lane >= o) x += y;
            }
            g_bsum[wid * 64 + idx] = carry + x - v;   // exclusive
            carry += __shfl_sync(0xffffffffu, x, 31);
        }
        if (lane == 0) {
            if (wid == 0)      g_rp_ap[NA] = carry;
            else if (wid == 1) g_rp_pa[NP] = carry;
            else               g_rp_pp[NP] = carry;
        }
    }
}

__global__ void scan_passC() {   // re-scan chunk, write rp, zero cnt
    int rel, chunk; rel_of(blockIdx.x, rel, chunk);
    int* cnt; int* rp; int n;
    if (rel == 0)      { cnt = g_cntA;  rp = g_rp_ap; n = NA; }
    else if (rel == 1) { cnt = g_cntP1; rp = g_rp_pa; n = NP; }
    else               { cnt = g_cntP2; rp = g_rp_pp; n = NP; }
    int tid = threadIdx.x, lane = tid & 31, wid = tid >> 5;
    int i0 = chunk * CH + tid * 8;
    int v[8];
    #pragma unroll
    for (int j = 0; j < 8; j++) v[j] = (i0 + j < n) ? cnt[i0 + j] : 0;
    int s = 0;
    #pragma unroll
    for (int j = 0; j < 8; j++) { int t = v[j]; v[j] = s; s += t; }
    int x = s;
    #pragma unroll
    for (int o = 1; o < 32; o <<= 1) {
        int y = __shfl_up_sync(0xffffffffu, x, o);
        if (lane >= o) x += y;
    }
    __shared__ int wsum[8];
    if (lane == 31) wsum[wid] = x;
    __syncthreads();
    if (wid == 0 && lane < 8) {
        int t = wsum[lane];
        int xx = t;
        #pragma unroll
        for (int o = 1; o < 8; o <<= 1) {
            int y = __shfl_up_sync(0xffu, xx, o);
            if (lane >= o) xx += y;
        }
        wsum[lane] = xx - t;
    }
    __syncthreads();
    int off = g_bsum[rel * 64 + chunk] + wsum[wid] + (x - s);
    #pragma unroll
    for (int j = 0; j < 8; j++) {
        int i = i0 + j;
        if (i < n) { rp[i] = off + v[j]; cnt[i] = 0; }
    }
}

__global__ void scatter_kernel(const int* __restrict__ ap_s, const int* __restrict__ ap_t,
                               const int* __restrict__ pa_s, const int* __restrict__ pa_t,
                               const int* __restrict__ pp_s, const int* __restrict__ pp_t) {
    const int Q = NE / 4;
    int i = blockIdx.x * blockDim.x + threadIdx.x;
    int stride = gridDim.x * blockDim.x;
    for (; i < 3 * Q; i += stride) {
        int4 sv, tv;
        int* cnt; const int* rp; int* ts;
        if (i < Q) {
            sv = ((const int4*)ap_s)[i]; tv = ((const int4*)ap_t)[i];
            cnt = g_cntA; rp = g_rp_ap; ts = g_ts_ap;
        } else if (i < 2 * Q) {
            sv = ((const int4*)pa_s)[i - Q]; tv = ((const int4*)pa_t)[i - Q];
            cnt = g_cntP1; rp = g_rp_pa; ts = g_ts_pa;
        } else {
            sv = ((const int4*)pp_s)[i - 2 * Q]; tv = ((const int4*)pp_t)[i - 2 * Q];
            cnt = g_cntP2; rp = g_rp_pp; ts = g_ts_pp;
        }
        int p0 = rp[sv.x] + atomicAdd(&cnt[sv.x], 1); ts[p0] = tv.x;
        int p1 = rp[sv.y] + atomicAdd(&cnt[sv.y], 1); ts[p1] = tv.y;
        int p2 = rp[sv.z] + atomicAdd(&cnt[sv.z], 1); ts[p2] = tv.z;
        int p3 = rp[sv.w] + atomicAdd(&cnt[sv.w], 1); ts[p3] = tv.w;
    }
}

// ---------------- projection GEMM via fp16 tensor cores (mma.sync m16n8k16) ----
__global__ __launch_bounds__(256) void proj_mma(
    const float* __restrict__ XA, const float* __restrict__ WA, const float* __restrict__ bA,
    const float* __restrict__ XP, const float* __restrict__ WP, const float* __restrict__ bP) {
    __shared__ __align__(16) __half as_[128 * AS_STRIDE];
    __shared__ __align__(16) __half2 bs[64 * 20];   // [n][k/2], K-chunk = 32

    int b = blockIdx.x;
    const float* X; const float* W; const float* bias; float* Y; __half2* Y16; int N, K, nb;
    if (b < GEMM_A_BLOCKS) {
        X = XA; W = WA; bias = bA; Y = g_xa; N = NA; K = DA; nb = b * 128;
        Y16 = g_h16a + (size_t)2 * NA * 32;
    } else {
        b -= GEMM_A_BLOCKS;
        X = XP; W = WP; bias = bP; Y = g_xp; N = NP; K = DP; nb = b * 128;
        Y16 = g_h16p + (size_t)2 * NP * 32;
    }

    int tid = threadIdx.x;
    int lane = tid & 31, w = tid >> 5;

    float acc[8][4];
    #pragma unroll
    for (int nt = 0; nt < 8; nt++)
        #pragma unroll
        for (int q = 0; q < 4; q++) acc[nt][q] = 0.f;

    for (int kc = 0; kc < K; kc += 32) {
        {
            int row = tid >> 1, kb16 = (tid & 1) * 16;
            int gn = nb + row;
            #pragma unroll
            for (int q = 0; q < 4; q++) {
                float4 v = (gn < N) ? *(const float4*)&X[(size_t)gn * K + kc + kb16 + q * 4]
                                    : make_float4(0.f, 0.f, 0.f, 0.f);
                uint2 st;
                st.x = h2u(__floats2half2_rn(v.x, v.y));
                st.y = h2u(__floats2half2_rn(v.z, v.w));
                *reinterpret_cast<uint2*>(&as_[row * AS_STRIDE + kb16 + q * 4]) = st;
            }
        }
        {
            int n = tid & 63, kk0 = (tid >> 6) * 2;
            #pragma unroll
            for (int it = 0; it < 4; it++) {
                int kk = kk0 + it * 8;
                float w0 = W[(size_t)(kc + kk) * 64 + n];
                float w1 = W[(size_t)(kc + kk + 1) * 64 + n];
                bs[n * 20 + (kk >> 1)] = __floats2half2_rn(w0, w1);
            }
        }
        __syncthreads();
        int g = lane >> 2, q2 = (lane & 3) * 2;
        #pragma unroll
        for (int ks = 0; ks < 2; ks++) {
            int kb = ks * 16;
            const __half* ar0 = &as_[(16 * w + g) * AS_STRIDE + kb + q2];
            const __half* ar1 = &as_[(16 * w + g + 8) * AS_STRIDE + kb + q2];
            unsigned a0 = *reinterpret_cast<const unsigned*>(ar0);
            unsigned a2 = *reinterpret_cast<const unsigned*>(ar0 + 8);
            unsigned a1 = *reinterpret_cast<const unsigned*>(ar1);
            unsigned a3 = *reinterpret_cast<const unsigned*>(ar1 + 8);
            #pragma unroll
            for (int nt = 0; nt < 8; nt++) {
                int n = nt * 8 + (lane >> 2);
                unsigned b0 = h2u(bs[n * 20 + (kb >> 1) + (lane & 3)]);
                unsigned b1 = h2u(bs[n * 20 + (kb >> 1) + (lane & 3) + 4]);
                mma16816(acc[nt], a0, a1, a2, a3, b0, b1);
            }
        }
        __syncthreads();
    }

    int g = lane >> 2, q2 = (lane & 3) * 2;
    int row0 = nb + 16 * w + g, row1 = row0 + 8;
    #pragma unroll
    for (int nt = 0; nt < 8; nt++) {
        int col = nt * 8 + q2;
        float b0v = __ldg(&bias[col]), b1v = __ldg(&bias[col + 1]);
        if (row0 < N) {
            float y0 = fmaxf(acc[nt][0] + b0v, 0.f);
            float y1 = fmaxf(acc[nt][1] + b1v, 0.f);
            float2 f2 = {y0, y1};
            *reinterpret_cast<float2*>(&Y[(size_t)row0 * 64 + col]) = f2;
            *reinterpret_cast<unsigned*>(&Y16[(size_t)row0 * 32 + (col >> 1)]) =
                h2u(__floats2half2_rn(y0, y1));
        }
        if (row1 < N) {
            float y0 = fmaxf(acc[nt][2] + b0v, 0.f);
            float y1 = fmaxf(acc[nt][3] + b1v, 0.f);
            float2 f2 = {y0, y1};
            *reinterpret_cast<float2*>(&Y[(size_t)row1 * 64 + col]) = f2;
            *reinterpret_cast<unsigned*>(&Y16[(size_t)row1 * 32 + (col >> 1)]) =
                h2u(__floats2half2_rn(y0, y1));
        }
    }
}

// ---------------- upfront scalar projections ----------------
__global__ void sproj0_kernel(const float* __restrict__ a1ap, const float* __restrict__ a2ap,
                              const float* __restrict__ a1pa, const float* __restrict__ a2pa,
                              const float* __restrict__ a1pp, const float* __restrict__ a2pp) {
    int gw = (blockIdx.x * blockDim.x + threadIdx.x) >> 5;
    int lane = threadIdx.x & 31;
    if (gw < NA) {
        int n = gw;
        float x0 = g_xa[(size_t)n * 64 + lane], x1 = g_xa[(size_t)n * 64 + 32 + lane];
        #pragma unroll
        for (int h = 0; h < 3; h++) {
            float d1 = wred32(fmaf(x0, a1ap[h * 64 + lane], x1 * a1ap[h * 64 + 32 + lane]));
            float d2 = wred32(fmaf(x0, a2ap[h * 64 + lane], x1 * a2ap[h * 64 + 32 + lane]));
            if (lane == 0) { g_x1ap[h * NA + n] = d1; g_x2ap[h * NA + n] = d2; }
        }
        float d3 = wred32(fmaf(x0, a2pa[lane], x1 * a2pa[32 + lane]));
        if (lane == 0) g_h1pa[n] = d3;
    } else {
        int n = gw - NA;
        float x0 = g_xp[(size_t)n * 64 + lane], x1 = g_xp[(size_t)n * 64 + 32 + lane];
        #pragma unroll
        for (int h = 0; h < 3; h++) {
            float d1 = wred32(fmaf(x0, a1pa[h * 64 + lane], x1 * a1pa[h * 64 + 32 + lane]));
            float d2 = wred32(fmaf(x0, a2pa[h * 64 + lane], x1 * a2pa[h * 64 + 32 + lane]));
            float d3 = wred32(fmaf(x0, a1pp[h * 64 + lane], x1 * a1pp[h * 64 + 32 + lane]));
            float d4 = wred32(fmaf(x0, a2pp[h * 64 + lane], x1 * a2pp[h * 64 + 32 + lane]));
            if (lane == 0) {
                g_x1pa[h * NP + n] = d1; g_x2pa[h * NP + n] = d2;
                g_x1pp[h * NP + n] = d3; g_x2pp[h * NP + n] = d4;
            }
        }
        float d5 = wred32(fmaf(x0, a2ap[lane], x1 * a2ap[32 + lane]));
        float d6 = wred32(fmaf(x0, a2pp[lane], x1 * a2pp[32 + lane]));
        if (lane == 0) { g_h1ap[n] = d5; g_h1pp[n] = d6; }
    }
}

// ---------------- edge aggregation: 2 edges in flight, uint4 row loads ----------
// Each 16-lane half owns one node. Lane = (pair<<3)|sub8: lane sub8 of pair p
// accumulates the 16B slice [sub8*8 .. +7] of edges e0+p, e0+p+2, ...
__device__ __forceinline__ void relation_accum8(const int* __restrict__ rp,
                                                const int* __restrict__ ts,
                                                const uint4* __restrict__ h4,
                                                const float* __restrict__ h1arr,
                                                float x1, int n, int sub8, int pair,
                                                float acc8[8], float& div) {
    int e0 = __ldg(&rp[n]), end = __ldg(&rp[n + 1]);
    #pragma unroll 2
    for (int e = e0 + pair; e < end; e += 2) {
        int t = __ldg(&ts[e]);
        float w = lrelu_exp(x1 + __ldg(&h1arr[t]));
        uint4 rv = __ldg(&h4[(size_t)t * 8 + sub8]);
        float2 f0 = __half22float2(*reinterpret_cast<__half2*>(&rv.x));
        float2 f1 = __half22float2(*reinterpret_cast<__half2*>(&rv.y));
        float2 f2 = __half22float2(*reinterpret_cast<__half2*>(&rv.z));
        float2 f3 = __half22float2(*reinterpret_cast<__half2*>(&rv.w));
        acc8[0] = fmaf(w, f0.x, acc8[0]);
        acc8[1] = fmaf(w, f0.y, acc8[1]);
        acc8[2] = fmaf(w, f1.x, acc8[2]);
        acc8[3] = fmaf(w, f1.y, acc8[3]);
        acc8[4] = fmaf(w, f2.x, acc8[4]);
        acc8[5] = fmaf(w, f2.y, acc8[5]);
        acc8[6] = fmaf(w, f3.x, acc8[6]);
        acc8[7] = fmaf(w, f3.y, acc8[7]);
        div += w;
    }
}

__device__ __forceinline__ void combine8(float acc8[8], float& div) {
    #pragma unroll
    for (int j = 0; j < 8; j++)
        acc8[j] += __shfl_xor_sync(0xffffffffu, acc8[j], 8, 16);
    div += __shfl_xor_sync(0xffffffffu, div, 8, 16);
}

// hops 0 and 1: A + P aggregation, writes mirrors + next-hop h1 scalars
__global__ void agg_kernel(int curA, int curP, int nxt, int h1cur, int h1nxt, int hop,
                           const float* __restrict__ a2pa_nx,
                           const float* __restrict__ a2ap_nx,
                           const float* __restrict__ a2pp_nx) {
    int lane = threadIdx.x & 31;
    int sub8 = lane & 7;
    int pair = (lane >> 3) & 1;
    int half = lane >> 4;
    if (blockIdx.x < BA_BLOCKS) {
        int warp = (blockIdx.x * blockDim.x + threadIdx.x) >> 5;
        int n = warp * 2 + half;
        const uint4* __restrict__ h4 = reinterpret_cast<const uint4*>(bufP16(curP));
        const float* __restrict__ h1 = g_h1ap + (size_t)h1cur * NP;
        float x1 = g_x1ap[hop * NA + n];
        float acc8[8] = {0.f, 0.f, 0.f, 0.f, 0.f, 0.f, 0.f, 0.f};
        float div = 0.f;
        relation_accum8(g_rp_ap, g_ts_ap, h4, h1, x1, n, sub8, pair, acc8, div);
        combine8(acc8, div);
        float w2 = lrelu_exp(x1 + g_x2ap[hop * NA + n]);
        const float* xr = &g_xa[(size_t)n * 64 + sub8 * 8];
        float4 xv0 = *(const float4*)xr;
        float4 xv1 = *(const float4*)(xr + 4);
        acc8[0] = fmaf(w2, xv0.x, acc8[0]); acc8[1] = fmaf(w2, xv0.y, acc8[1]);
        acc8[2] = fmaf(w2, xv0.z, acc8[2]); acc8[3] = fmaf(w2, xv0.w, acc8[3]);
        acc8[4] = fmaf(w2, xv1.x, acc8[4]); acc8[5] = fmaf(w2, xv1.y, acc8[5]);
        acc8[6] = fmaf(w2, xv1.z, acc8[6]); acc8[7] = fmaf(w2, xv1.w, acc8[7]);
        div += w2;
        float inv = 1.f / div;
        float r8[8];
        #pragma unroll
        for (int j = 0; j < 8; j++) r8[j] = eluf(acc8[j] * inv);
        if (pair == 0) {
            uint4 st;
            st.x = h2u(__floats2half2_rn(r8[0], r8[1]));
            st.y = h2u(__floats2half2_rn(r8[2], r8[3]));
            st.z = h2u(__floats2half2_rn(r8[4], r8[5]));
            st.w = h2u(__floats2half2_rn(r8[6], r8[7]));
            uint4* mrow = reinterpret_cast<uint4*>(&g_h16a[((size_t)nxt * NA + n) * 32]);
            mrow[sub8] = st;
        }
        const float* va = &a2pa_nx[sub8 * 8];
        float4 va0 = *(const float4*)va, va1 = *(const float4*)(va + 4);
        float p = r8[0] * va0.x + r8[1] * va0.y + r8[2] * va0.z + r8[3] * va0.w
                + r8[4] * va1.x + r8[5] * va1.y + r8[6] * va1.z + r8[7] * va1.w;
        p = wred8(p);
        if ((lane & 15) == 0) g_h1pa[(size_t)h1nxt * NA + n] = p;
    } else {
        int warp = ((blockIdx.x - BA_BLOCKS) * blockDim.x + threadIdx.x) >> 5;
        int n = warp * 2 + half;
        const uint4* __restrict__ hA4 = reinterpret_cast<const uint4*>(bufA16(curA));
        const uint4* __restrict__ hP4 = reinterpret_cast<const uint4*>(bufP16(curP));
        const float* __restrict__ h1a = g_h1pa + (size_t)h1cur * NA;
        const float* __restrict__ h1p = g_h1pp + (size_t)h1cur * NP;
        float x1a = g_x1pa[hop * NP + n];
        float x1p = g_x1pp[hop * NP + n];
        float acc1[8] = {0.f, 0.f, 0.f, 0.f, 0.f, 0.f, 0.f, 0.f};
        float acc2[8] = {0.f, 0.f, 0.f, 0.f, 0.f, 0.f, 0.f, 0.f};
        float div1 = 0.f, div2 = 0.f;
        relation_accum8(g_rp_pa, g_ts_pa, hA4, h1a, x1a, n, sub8, pair, acc1, div1);
        relation_accum8(g_rp_pp, g_ts_pp, hP4, h1p, x1p, n, sub8, pair, acc2, div2);
        combine8(acc1, div1);
        combine8(acc2, div2);
        const float* xr = &g_xp[(size_t)n * 64 + sub8 * 8];
        float4 xv0 = *(const float4*)xr;
        float4 xv1 = *(const float4*)(xr + 4);
        float w2a = lrelu_exp(x1a + g_x2pa[hop * NP + n]);
        float w2p = lrelu_exp(x1p + g_x2pp[hop * NP + n]);
        acc1[0] = fmaf(w2a, xv0.x, acc1[0]); acc1[1] = fmaf(w2a, xv0.y, acc1[1]);
        acc1[2] = fmaf(w2a, xv0.z, acc1[2]); acc1[3] = fmaf(w2a, xv0.w, acc1[3]);
        acc1[4] = fmaf(w2a, xv1.x, acc1[4]); acc1[5] = fmaf(w2a, xv1.y, acc1[5]);
        acc1[6] = fmaf(w2a, xv1.z, acc1[6]); acc1[7] = fmaf(w2a, xv1.w, acc1[7]);
        div1 += w2a;
        acc2[0] = fmaf(w2p, xv0.x, acc2[0]); acc2[1] = fmaf(w2p, xv0.y, acc2[1]);
        acc2[2] = fmaf(w2p, xv0.z, acc2[2]); acc2[3] = fmaf(w2p, xv0.w, acc2[3]);
        acc2[4] = fmaf(w2p, xv1.x, acc2[4]); acc2[5] = fmaf(w2p, xv1.y, acc2[5]);
        acc2[6] = fmaf(w2p, xv1.z, acc2[6]); acc2[7] = fmaf(w2p, xv1.w, acc2[7]);
        div2 += w2p;
        float i1 = 1.f / div1, i2 = 1.f / div2;
        float r8[8];
        #pragma unroll
        for (int j = 0; j < 8; j++) r8[j] = eluf(0.5f * (acc1[j] * i1 + acc2[j] * i2));
        if (pair == 0) {
            uint4 st;
            st.x = h2u(__floats2half2_rn(r8[0], r8[1]));
            st.y = h2u(__floats2half2_rn(r8[2], r8[3]));
            st.z = h2u(__floats2half2_rn(r8[4], r8[5]));
            st.w = h2u(__floats2half2_rn(r8[6], r8[7]));
            uint4* mrow = reinterpret_cast<uint4*>(&g_h16p[((size_t)nxt * NP + n) * 32]);
            mrow[sub8] = st;
        }
        const float* va = &a2ap_nx[sub8 * 8];
        const float* vp = &a2pp_nx[sub8 * 8];
        float4 va0 = *(const float4*)va, va1 = *(const float4*)(va + 4);
        float4 vp0 = *(const float4*)vp, vp1 = *(const float4*)(vp + 4);
        float p1 = r8[0] * va0.x + r8[1] * va0.y + r8[2] * va0.z + r8[3] * va0.w
                 + r8[4] * va1.x + r8[5] * va1.y + r8[6] * va1.z + r8[7] * va1.w;
        float p2 = r8[0] * vp0.x + r8[1] * vp0.y + r8[2] * vp0.z + r8[3] * vp0.w
                 + r8[4] * vp1.x + r8[5] * vp1.y + r8[6] * vp1.z + r8[7] * vp1.w;
        p1 = wred8(p1);
        p2 = wred8(p2);
        if ((lane & 15) == 0) {
            g_h1ap[(size_t)h1nxt * NP + n] = p1;
            g_h1pp[(size_t)h1nxt * NP + n] = p2;
        }
    }
}

// last hop: A-side aggregation only, with fc2 fused
__global__ void aggA_fc2_kernel(int curP, int h1cur,
                                const float* __restrict__ W,
                                const float* __restrict__ bias,
                                float* __restrict__ out) {
    __shared__ __align__(16) float wt[16 * 68];      // transposed W, padded stride
    __shared__ __align__(16) float rs[8][2][64];     // per-warp per-half h_a row
    int tid = threadIdx.x;
    for (int idx = tid; idx < 1024; idx += 256) {
        int k = idx >> 4, j = idx & 15;
        wt[j * 68 + k] = W[idx];
    }
    __syncthreads();

    int lane = tid & 31, sub8 = lane & 7, pair = (lane >> 3) & 1, half = lane >> 4;
    int w = tid >> 5;
    int warp = (blockIdx.x * blockDim.x + tid) >> 5;
    int n = warp * 2 + half;

    const uint4* __restrict__ h4 = reinterpret_cast<const uint4*>(bufP16(curP));
    const float* __restrict__ h1 = g_h1ap + (size_t)h1cur * NP;
    float x1 = g_x1ap[2 * NA + n];
    float acc8[8] = {0.f, 0.f, 0.f, 0.f, 0.f, 0.f, 0.f, 0.f};
    float div = 0.f;
    relation_accum8(g_rp_ap, g_ts_ap, h4, h1, x1, n, sub8, pair, acc8, div);
    combine8(acc8, div);
    float w2 = lrelu_exp(x1 + g_x2ap[2 * NA + n]);
    const float* xr = &g_xa[(size_t)n * 64 + sub8 * 8];
    float4 xv0 = *(const float4*)xr;
    float4 xv1 = *(const float4*)(xr + 4);
    acc8[0] = fmaf(w2, xv0.x, acc8[0]); acc8[1] = fmaf(w2, xv0.y, acc8[1]);
    acc8[2] = fmaf(w2, xv0.z, acc8[2]); acc8[3] = fmaf(w2, xv0.w, acc8[3]);
    acc8[4] = fmaf(w2, xv1.x, acc8[4]); acc8[5] = fmaf(w2, xv1.y, acc8[5]);
    acc8[6] = fmaf(w2, xv1.z, acc8[6]); acc8[7] = fmaf(w2, xv1.w, acc8[7]);
    div += w2;
    float inv = 1.f / div;
    float r8[8];
    #pragma unroll
    for (int j = 0; j < 8; j++) r8[j] = eluf(acc8[j] * inv);

    if (pair == 0) {
        float4 s0 = {r8[0], r8[1], r8[2], r8[3]};
        float4 s1 = {r8[4], r8[5], r8[6], r8[7]};
        *reinterpret_cast<float4*>(&rs[w][half][sub8 * 8]) = s0;
        *reinterpret_cast<float4*>(&rs[w][half][sub8 * 8 + 4]) = s1;
    }
    __syncwarp();
    int sub = lane & 15;
    float o = bias[sub];
    #pragma unroll
    for (int k4 = 0; k4 < 16; k4++) {
        float4 rv = *reinterpret_cast<const float4*>(&rs[w][half][k4 * 4]);
        float4 wv = *reinterpret_cast<const float4*>(&wt[sub * 68 + k4 * 4]);
        o += rv.x * wv.x + rv.y * wv.y + rv.z * wv.z + rv.w * wv.w;
    }
    out[(size_t)n * 16 + sub] = o;
}

// ---------------- launch ----------------
extern "C" void kernel_launch(void* const* d_in, const int* in_sizes, int n_in,
                              void* d_out, int out_size) {
    const float* x_a   = (const float*)d_in[0];
    const float* x_p   = (const float*)d_in[1];
    const int* ap_s    = (const int*)d_in[2];
    const int* ap_t    = (const int*)d_in[3];
    const int* pa_s    = (const int*)d_in[4];
    const int* pa_t    = (const int*)d_in[5];
    const int* pp_s    = (const int*)d_in[6];
    const int* pp_t    = (const int*)d_in[7];
    const float* fc1aw = (const float*)d_in[8];
    const float* fc1ab = (const float*)d_in[9];
    const float* fc1pw = (const float*)d_in[10];
    const float* fc1pb = (const float*)d_in[11];
    const float* fc2w  = (const float*)d_in[12];
    const float* fc2b  = (const float*)d_in[13];
    const float* a1ap  = (const float*)d_in[14];
    const float* a2ap  = (const float*)d_in[15];
    const float* a1pa  = (const float*)d_in[16];
    const float* a2pa  = (const float*)d_in[17];
    const float* a1pp  = (const float*)d_in[18];
    const float* a2pp  = (const float*)d_in[19];
    float* out = (float*)d_out;

    static cudaStream_t s2 = nullptr;
    static cudaEvent_t evF = nullptr, evJ = nullptr;
    if (s2 == nullptr) {
        cudaStreamCreateWithFlags(&s2, cudaStreamNonBlocking);
        cudaEventCreateWithFlags(&evF, cudaEventDisableTiming);
        cudaEventCreateWithFlags(&evJ, cudaEventDisableTiming);
    }

    // ---- fork: projection chain on s2, CSR chain on the main stream ----
    cudaEventRecord(evF, 0);
    cudaStreamWaitEvent(s2, evF, 0);

    proj_mma<<<GEMM_A_BLOCKS + GEMM_P_BLOCKS, 256, 0, s2>>>(x_a, fc1aw, fc1ab, x_p, fc1pw, fc1pb);
    sproj0_kernel<<<(NA + NP) / 8, 256, 0, s2>>>(a1ap, a2ap, a1pa, a2pa, a1pp, a2pp);
    cudaEventRecord(evJ, s2);

    // CSR build (main stream, overlapped)
    zero_cnt_kernel<<<977, 256>>>();
    hist_kernel<<<1024, 256>>>(ap_s, pa_s, pp_s);
    scan_passA<<<NBLK_SCAN, 256>>>();
    scan_passB<<<1, 96>>>();
    scan_passC<<<NBLK_SCAN, 256>>>();
    scatter_kernel<<<1500, 256>>>(ap_s, ap_t, pa_s, pa_t, pp_s, pp_t);

    // ---- join ----
    cudaStreamWaitEvent(0, evJ, 0);

    // hops 0 and 1 (full A+P), hop 2 (A only, fc2 fused)
    agg_kernel<<<BA_BLOCKS + BP_BLOCKS, 256>>>(2, 2, 0, 0, 1, 0,
                                               a2pa + 64, a2ap + 64, a2pp + 64);
    agg_kernel<<<BA_BLOCKS + BP_BLOCKS, 256>>>(0, 0, 1, 1, 0, 1,
                                               a2pa + 128, a2ap + 128, a2pp + 128);
    aggA_fc2_kernel<<<BA_BLOCKS, 256>>>(1, 0, fc2w, fc2b, out);
}

// round 14
// speedup vs baseline: 1.3778x; 1.0222x over previous
#include <cuda_runtime.h>
#include <cuda_fp16.h>
#include <cuda_bf16.h>
#include <math.h>

#define NA 50000
#define NP 100000
#define DA 512
#define DP 256
#define HID 64
#define NOUT 16
#define NE 2000000
#define CH 2048
#define NCH_A 25
#define NCH_P 49
#define NBLK_SCAN (NCH_A + 2*NCH_P)   // 123
#define BA_BLOCKS 3125   // NA/2 nodes -> 25000 warps
#define BP_BLOCKS 6250
#define GEMM_A_BLOCKS 391  // ceil(50000/128)
#define GEMM_P_BLOCKS 782  // ceil(100000/128)
#define AS_STRIDE 40       // halves per row in A-stage smem (conflict-free)

// ---------------- scratch ----------------
__device__ float g_xa[NA * HID];
__device__ float g_xp[NP * HID];
// fp16 gather mirrors; buffer index 2 == x mirror
__device__ __align__(16) __half2 g_h16a[3 * NA * 32];
__device__ __align__(16) __half2 g_h16p[3 * NP * 32];

__device__ int g_rp_ap[NA + 1];
__device__ int g_rp_pa[NP + 1];
__device__ int g_rp_pp[NP + 1];
__device__ int g_ts_ap[NE];
__device__ int g_ts_pa[NE];
__device__ int g_ts_pp[NE];
__device__ int g_cntA[NA];
__device__ int g_cntP1[NP];
__device__ int g_cntP2[NP];
__device__ int g_bsum[3 * 64];

// x-based attention scalars, all hops precomputed
__device__ float g_x1ap[3 * NA], g_x2ap[3 * NA];
__device__ float g_x1pa[3 * NP], g_x2pa[3 * NP], g_x1pp[3 * NP], g_x2pp[3 * NP];
// h-based scalars, double buffered
__device__ float g_h1pa[2 * NA];
__device__ float g_h1ap[2 * NP], g_h1pp[2 * NP];

// ---------------- helpers ----------------
__device__ __forceinline__ const __half2* bufA16(int c) { return g_h16a + (size_t)c * NA * 32; }
__device__ __forceinline__ const __half2* bufP16(int c) { return g_h16p + (size_t)c * NP * 32; }
__device__ __forceinline__ float eluf(float v) { return v > 0.f ? v : expm1f(v); }
__device__ __forceinline__ float lrelu_exp(float sc) {
    sc = sc >= 0.f ? sc : 0.2f * sc;
    return __expf(sc);
}
__device__ __forceinline__ float wred32(float v) {
    v += __shfl_down_sync(0xffffffffu, v, 16);
    v += __shfl_down_sync(0xffffffffu, v, 8);
    v += __shfl_down_sync(0xffffffffu, v, 4);
    v += __shfl_down_sync(0xffffffffu, v, 2);
    v += __shfl_down_sync(0xffffffffu, v, 1);
    return v;
}
__device__ __forceinline__ float wred8(float v) {
    v += __shfl_down_sync(0xffffffffu, v, 4, 8);
    v += __shfl_down_sync(0xffffffffu, v, 2, 8);
    v += __shfl_down_sync(0xffffffffu, v, 1, 8);
    return v;
}
__device__ __forceinline__ unsigned h2u(__half2 h) { return *reinterpret_cast<unsigned*>(&h); }
__device__ __forceinline__ void mma16816(float* d, unsigned a0, unsigned a1, unsigned a2, unsigned a3,
                                         unsigned b0, unsigned b1) {
    asm volatile(
        "mma.sync.aligned.m16n8k16.row.col.f32.f16.f16.f32 "
        "{%0,%1,%2,%3}, {%4,%5,%6,%7}, {%8,%9}, {%0,%1,%2,%3};"
        : "+f"(d[0]), "+f"(d[1]), "+f"(d[2]), "+f"(d[3])
        : "r"(a0), "r"(a1), "r"(a2), "r"(a3), "r"(b0), "r"(b1));
}

// ---------------- CSR build ----------------
__global__ void zero_cnt_kernel() {
    int i = blockIdx.x * blockDim.x + threadIdx.x;
    int stride = gridDim.x * blockDim.x;
    for (; i < NA + 2 * NP; i += stride) {
        if (i < NA) g_cntA[i] = 0;
        else if (i < NA + NP) g_cntP1[i - NA] = 0;
        else g_cntP2[i - NA - NP] = 0;
    }
}

__global__ void hist_kernel(const int* __restrict__ ap_s,
                            const int* __restrict__ pa_s,
                            const int* __restrict__ pp_s) {
    const int Q = NE / 4;
    int i = blockIdx.x * blockDim.x + threadIdx.x;
    int stride = gridDim.x * blockDim.x;
    for (; i < 3 * Q; i += stride) {
        int4 v;
        int* cnt;
        if (i < Q)          { v = ((const int4*)ap_s)[i];        cnt = g_cntA;  }
        else if (i < 2 * Q) { v = ((const int4*)pa_s)[i - Q];    cnt = g_cntP1; }
        else                { v = ((const int4*)pp_s)[i - 2 * Q]; cnt = g_cntP2; }
        atomicAdd(&cnt[v.x], 1);
        atomicAdd(&cnt[v.y], 1);
        atomicAdd(&cnt[v.z], 1);
        atomicAdd(&cnt[v.w], 1);
    }
}

__device__ __forceinline__ void rel_of(int b, int& rel, int& chunk) {
    if (b < NCH_A)              { rel = 0; chunk = b; }
    else if (b < NCH_A + NCH_P) { rel = 1; chunk = b - NCH_A; }
    else                        { rel = 2; chunk = b - NCH_A - NCH_P; }
}

__global__ void scan_passA() {
    int rel, chunk; rel_of(blockIdx.x, rel, chunk);
    const int* cnt = rel == 0 ? g_cntA : (rel == 1 ? g_cntP1 : g_cntP2);
    int n = rel == 0 ? NA : NP;
    int base = chunk * CH;
    int s = 0;
    #pragma unroll
    for (int j = 0; j < 8; j++) {
        int i = base + threadIdx.x + 256 * j;
        if (i < n) s += cnt[i];
    }
    #pragma unroll
    for (int o = 16; o; o >>= 1) s += __shfl_down_sync(0xffffffffu, s, o);
    __shared__ int sh[8];
    int lane = threadIdx.x & 31, wid = threadIdx.x >> 5;
    if (lane == 0) sh[wid] = s;
    __syncthreads();
    if (wid == 0) {
        int t = (lane < 8) ? sh[lane] : 0;
        #pragma unroll
        for (int o = 4; o; o >>= 1) t += __shfl_down_sync(0xffffffffu, t, o);
        if (lane == 0) g_bsum[rel * 64 + chunk] = t;
    }
}

__global__ void scan_passB() {   // 1 block, 96 threads
    int wid = threadIdx.x >> 5, lane = threadIdx.x & 31;
    if (wid < 3) {
        int nch = (wid == 0) ? NCH_A : NCH_P;
        int carry = 0;
        #pragma unroll
        for (int c0 = 0; c0 < 64; c0 += 32) {
            int idx = c0 + lane;
            int v = (idx < nch) ? g_bsum[wid * 64 + idx] : 0;
            int x = v;
            #pragma unroll
            for (int o = 1; o < 32; o <<= 1) {
                int y = __shfl_up_sync(0xffffffffu, x, o);
                if (lane >= o) x += y;
            }
            g_bsum[wid * 64 + idx] = carry + x - v;   // exclusive
            carry += __shfl_sync(0xffffffffu, x, 31);
        }
        if (lane == 0) {
            if (wid == 0)      g_rp_ap[NA] = carry;
            else if (wid == 1) g_rp_pa[NP] = carry;
            else               g_rp_pp[NP] = carry;
        }
    }
}

__global__ void scan_passC() {   // re-scan chunk, write rp, zero cnt
    int rel, chunk; rel_of(blockIdx.x, rel, chunk);
    int* cnt; int* rp; int n;
    if (rel == 0)      { cnt = g_cntA;  rp = g_rp_ap; n = NA; }
    else if (rel == 1) { cnt = g_cntP1; rp = g_rp_pa; n = NP; }
    else               { cnt = g_cntP2; rp = g_rp_pp; n = NP; }
    int tid = threadIdx.x, lane = tid & 31, wid = tid >> 5;
    int i0 = chunk * CH + tid * 8;
    int v[8];
    #pragma unroll
    for (int j = 0; j < 8; j++) v[j] = (i0 + j < n) ? cnt[i0 + j] : 0;
    int s = 0;
    #pragma unroll
    for (int j = 0; j < 8; j++) { int t = v[j]; v[j] = s; s += t; }
    int x = s;
    #pragma unroll
    for (int o = 1; o < 32; o <<= 1) {
        int y = __shfl_up_sync(0xffffffffu, x, o);
        if (lane >= o) x += y;
    }
    __shared__ int wsum[8];
    if (lane == 31) wsum[wid] = x;
    __syncthreads();
    if (wid == 0 && lane < 8) {
        int t = wsum[lane];
        int xx = t;
        #pragma unroll
        for (int o = 1; o < 8; o <<= 1) {
            int y = __shfl_up_sync(0xffu, xx, o);
            if (lane >= o) xx += y;
        }
        wsum[lane] = xx - t;
    }
    __syncthreads();
    int off = g_bsum[rel * 64 + chunk] + wsum[wid] + (x - s);
    #pragma unroll
    for (int j = 0; j < 8; j++) {
        int i = i0 + j;
        if (i < n) { rp[i] = off + v[j]; cnt[i] = 0; }
    }
}

__global__ void scatter_ap_kernel(const int* __restrict__ ap_s, const int* __restrict__ ap_t) {
    const int Q = NE / 4;
    int i = blockIdx.x * blockDim.x + threadIdx.x;
    int stride = gridDim.x * blockDim.x;
    for (; i < Q; i += stride) {
        int4 sv = ((const int4*)ap_s)[i];
        int4 tv = ((const int4*)ap_t)[i];
        int p0 = g_rp_ap[sv.x] + atomicAdd(&g_cntA[sv.x], 1); g_ts_ap[p0] = tv.x;
        int p1 = g_rp_ap[sv.y] + atomicAdd(&g_cntA[sv.y], 1); g_ts_ap[p1] = tv.y;
        int p2 = g_rp_ap[sv.z] + atomicAdd(&g_cntA[sv.z], 1); g_ts_ap[p2] = tv.z;
        int p3 = g_rp_ap[sv.w] + atomicAdd(&g_cntA[sv.w], 1); g_ts_ap[p3] = tv.w;
    }
}

__global__ void scatter_papp_kernel(const int* __restrict__ pa_s, const int* __restrict__ pa_t,
                                    const int* __restrict__ pp_s, const int* __restrict__ pp_t) {
    const int Q = NE / 4;
    int i = blockIdx.x * blockDim.x + threadIdx.x;
    int stride = gridDim.x * blockDim.x;
    for (; i < 2 * Q; i += stride) {
        int4 sv, tv;
        int* cnt; const int* rp; int* ts;
        if (i < Q) {
            sv = ((const int4*)pa_s)[i]; tv = ((const int4*)pa_t)[i];
            cnt = g_cntP1; rp = g_rp_pa; ts = g_ts_pa;
        } else {
            sv = ((const int4*)pp_s)[i - Q]; tv = ((const int4*)pp_t)[i - Q];
            cnt = g_cntP2; rp = g_rp_pp; ts = g_ts_pp;
        }
        int p0 = rp[sv.x] + atomicAdd(&cnt[sv.x], 1); ts[p0] = tv.x;
        int p1 = rp[sv.y] + atomicAdd(&cnt[sv.y], 1); ts[p1] = tv.y;
        int p2 = rp[sv.z] + atomicAdd(&cnt[sv.z], 1); ts[p2] = tv.z;
        int p3 = rp[sv.w] + atomicAdd(&cnt[sv.w], 1); ts[p3] = tv.w;
    }
}

// ---------------- projection GEMM via fp16 tensor cores (mma.sync m16n8k16) ----
__global__ __launch_bounds__(256) void proj_mma(
    const float* __restrict__ XA, const float* __restrict__ WA, const float* __restrict__ bA,
    const float* __restrict__ XP, const float* __restrict__ WP, const float* __restrict__ bP) {
    __shared__ __align__(16) __half as_[128 * AS_STRIDE];
    __shared__ __align__(16) __half2 bs[64 * 20];   // [n][k/2], K-chunk = 32

    int b = blockIdx.x;
    const float* X; const float* W; const float* bias; float* Y; __half2* Y16; int N, K, nb;
    if (b < GEMM_A_BLOCKS) {
        X = XA; W = WA; bias = bA; Y = g_xa; N = NA; K = DA; nb = b * 128;
        Y16 = g_h16a + (size_t)2 * NA * 32;
    } else {
        b -= GEMM_A_BLOCKS;
        X = XP; W = WP; bias = bP; Y = g_xp; N = NP; K = DP; nb = b * 128;
        Y16 = g_h16p + (size_t)2 * NP * 32;
    }

    int tid = threadIdx.x;
    int lane = tid & 31, w = tid >> 5;

    float acc[8][4];
    #pragma unroll
    for (int nt = 0; nt < 8; nt++)
        #pragma unroll
        for (int q = 0; q < 4; q++) acc[nt][q] = 0.f;

    for (int kc = 0; kc < K; kc += 32) {
        {
            int row = tid >> 1, kb16 = (tid & 1) * 16;
            int gn = nb + row;
            #pragma unroll
            for (int q = 0; q < 4; q++) {
                float4 v = (gn < N) ? *(const float4*)&X[(size_t)gn * K + kc + kb16 + q * 4]
                                    : make_float4(0.f, 0.f, 0.f, 0.f);
                uint2 st;
                st.x = h2u(__floats2half2_rn(v.x, v.y));
                st.y = h2u(__floats2half2_rn(v.z, v.w));
                *reinterpret_cast<uint2*>(&as_[row * AS_STRIDE + kb16 + q * 4]) = st;
            }
        }
        {
            int n = tid & 63, kk0 = (tid >> 6) * 2;
            #pragma unroll
            for (int it = 0; it < 4; it++) {
                int kk = kk0 + it * 8;
                float w0 = W[(size_t)(kc + kk) * 64 + n];
                float w1 = W[(size_t)(kc + kk + 1) * 64 + n];
                bs[n * 20 + (kk >> 1)] = __floats2half2_rn(w0, w1);
            }
        }
        __syncthreads();
        int g = lane >> 2, q2 = (lane & 3) * 2;
        #pragma unroll
        for (int ks = 0; ks < 2; ks++) {
            int kb = ks * 16;
            const __half* ar0 = &as_[(16 * w + g) * AS_STRIDE + kb + q2];
            const __half* ar1 = &as_[(16 * w + g + 8) * AS_STRIDE + kb + q2];
            unsigned a0 = *reinterpret_cast<const unsigned*>(ar0);
            unsigned a2 = *reinterpret_cast<const unsigned*>(ar0 + 8);
            unsigned a1 = *reinterpret_cast<const unsigned*>(ar1);
            unsigned a3 = *reinterpret_cast<const unsigned*>(ar1 + 8);
            #pragma unroll
            for (int nt = 0; nt < 8; nt++) {
                int n = nt * 8 + (lane >> 2);
                unsigned b0 = h2u(bs[n * 20 + (kb >> 1) + (lane & 3)]);
                unsigned b1 = h2u(bs[n * 20 + (kb >> 1) + (lane & 3) + 4]);
                mma16816(acc[nt], a0, a1, a2, a3, b0, b1);
            }
        }
        __syncthreads();
    }

    int g = lane >> 2, q2 = (lane & 3) * 2;
    int row0 = nb + 16 * w + g, row1 = row0 + 8;
    #pragma unroll
    for (int nt = 0; nt < 8; nt++) {
        int col = nt * 8 + q2;
        float b0v = __ldg(&bias[col]), b1v = __ldg(&bias[col + 1]);
        if (row0 < N) {
            float y0 = fmaxf(acc[nt][0] + b0v, 0.f);
            float y1 = fmaxf(acc[nt][1] + b1v, 0.f);
            float2 f2 = {y0, y1};
            *reinterpret_cast<float2*>(&Y[(size_t)row0 * 64 + col]) = f2;
            *reinterpret_cast<unsigned*>(&Y16[(size_t)row0 * 32 + (col >> 1)]) =
                h2u(__floats2half2_rn(y0, y1));
        }
        if (row1 < N) {
            float y0 = fmaxf(acc[nt][2] + b0v, 0.f);
            float y1 = fmaxf(acc[nt][3] + b1v, 0.f);
            float2 f2 = {y0, y1};
            *reinterpret_cast<float2*>(&Y[(size_t)row1 * 64 + col]) = f2;
            *reinterpret_cast<unsigned*>(&Y16[(size_t)row1 * 32 + (col >> 1)]) =
                h2u(__floats2half2_rn(y0, y1));
        }
    }
}

// ---------------- upfront scalar projections ----------------
__global__ void sproj0_kernel(const float* __restrict__ a1ap, const float* __restrict__ a2ap,
                              const float* __restrict__ a1pa, const float* __restrict__ a2pa,
                              const float* __restrict__ a1pp, const float* __restrict__ a2pp) {
    int gw = (blockIdx.x * blockDim.x + threadIdx.x) >> 5;
    int lane = threadIdx.x & 31;
    if (gw < NA) {
        int n = gw;
        float x0 = g_xa[(size_t)n * 64 + lane], x1 = g_xa[(size_t)n * 64 + 32 + lane];
        #pragma unroll
        for (int h = 0; h < 3; h++) {
            float d1 = wred32(fmaf(x0, a1ap[h * 64 + lane], x1 * a1ap[h * 64 + 32 + lane]));
            float d2 = wred32(fmaf(x0, a2ap[h * 64 + lane], x1 * a2ap[h * 64 + 32 + lane]));
            if (lane == 0) { g_x1ap[h * NA + n] = d1; g_x2ap[h * NA + n] = d2; }
        }
        float d3 = wred32(fmaf(x0, a2pa[lane], x1 * a2pa[32 + lane]));
        if (lane == 0) g_h1pa[n] = d3;
    } else {
        int n = gw - NA;
        float x0 = g_xp[(size_t)n * 64 + lane], x1 = g_xp[(size_t)n * 64 + 32 + lane];
        #pragma unroll
        for (int h = 0; h < 3; h++) {
            float d1 = wred32(fmaf(x0, a1pa[h * 64 + lane], x1 * a1pa[h * 64 + 32 + lane]));
            float d2 = wred32(fmaf(x0, a2pa[h * 64 + lane], x1 * a2pa[h * 64 + 32 + lane]));
            float d3 = wred32(fmaf(x0, a1pp[h * 64 + lane], x1 * a1pp[h * 64 + 32 + lane]));
            float d4 = wred32(fmaf(x0, a2pp[h * 64 + lane], x1 * a2pp[h * 64 + 32 + lane]));
            if (lane == 0) {
                g_x1pa[h * NP + n] = d1; g_x2pa[h * NP + n] = d2;
                g_x1pp[h * NP + n] = d3; g_x2pp[h * NP + n] = d4;
            }
        }
        float d5 = wred32(fmaf(x0, a2ap[lane], x1 * a2ap[32 + lane]));
        float d6 = wred32(fmaf(x0, a2pp[lane], x1 * a2pp[32 + lane]));
        if (lane == 0) { g_h1ap[n] = d5; g_h1pp[n] = d6; }
    }
}

// ---------------- edge aggregation: 2 edges in flight, uint4 row loads ----------
__device__ __forceinline__ void relation_accum8(const int* __restrict__ rp,
                                                const int* __restrict__ ts,
                                                const uint4* __restrict__ h4,
                                                const float* __restrict__ h1arr,
                                                float x1, int n, int sub8, int pair,
                                                float acc8[8], float& div) {
    int e0 = __ldg(&rp[n]), end = __ldg(&rp[n + 1]);
    #pragma unroll 2
    for (int e = e0 + pair; e < end; e += 2) {
        int t = __ldg(&ts[e]);
        float w = lrelu_exp(x1 + __ldg(&h1arr[t]));
        uint4 rv = __ldg(&h4[(size_t)t * 8 + sub8]);
        float2 f0 = __half22float2(*reinterpret_cast<__half2*>(&rv.x));
        float2 f1 = __half22float2(*reinterpret_cast<__half2*>(&rv.y));
        float2 f2 = __half22float2(*reinterpret_cast<__half2*>(&rv.z));
        float2 f3 = __half22float2(*reinterpret_cast<__half2*>(&rv.w));
        acc8[0] = fmaf(w, f0.x, acc8[0]);
        acc8[1] = fmaf(w, f0.y, acc8[1]);
        acc8[2] = fmaf(w, f1.x, acc8[2]);
        acc8[3] = fmaf(w, f1.y, acc8[3]);
        acc8[4] = fmaf(w, f2.x, acc8[4]);
        acc8[5] = fmaf(w, f2.y, acc8[5]);
        acc8[6] = fmaf(w, f3.x, acc8[6]);
        acc8[7] = fmaf(w, f3.y, acc8[7]);
        div += w;
    }
}

__device__ __forceinline__ void combine8(float acc8[8], float& div) {
    #pragma unroll
    for (int j = 0; j < 8; j++)
        acc8[j] += __shfl_xor_sync(0xffffffffu, acc8[j], 8, 16);
    div += __shfl_xor_sync(0xffffffffu, div, 8, 16);
}

// A-side aggregation for one hop (writes mirror nxt + h1pa[h1nxt])
__device__ __forceinline__ void aggA_body(int warp, int lane, int curP, int nxt,
                                          int h1cur, int h1nxt, int hop,
                                          const float* __restrict__ a2pa_nx) {
    int sub8 = lane & 7, pair = (lane >> 3) & 1, half = lane >> 4;
    int n = warp * 2 + half;
    const uint4* __restrict__ h4 = reinterpret_cast<const uint4*>(bufP16(curP));
    const float* __restrict__ h1 = g_h1ap + (size_t)h1cur * NP;
    float x1 = g_x1ap[hop * NA + n];
    float acc8[8] = {0.f, 0.f, 0.f, 0.f, 0.f, 0.f, 0.f, 0.f};
    float div = 0.f;
    relation_accum8(g_rp_ap, g_ts_ap, h4, h1, x1, n, sub8, pair, acc8, div);
    combine8(acc8, div);
    float w2 = lrelu_exp(x1 + g_x2ap[hop * NA + n]);
    const float* xr = &g_xa[(size_t)n * 64 + sub8 * 8];
    float4 xv0 = *(const float4*)xr;
    float4 xv1 = *(const float4*)(xr + 4);
    acc8[0] = fmaf(w2, xv0.x, acc8[0]); acc8[1] = fmaf(w2, xv0.y, acc8[1]);
    acc8[2] = fmaf(w2, xv0.z, acc8[2]); acc8[3] = fmaf(w2, xv0.w, acc8[3]);
    acc8[4] = fmaf(w2, xv1.x, acc8[4]); acc8[5] = fmaf(w2, xv1.y, acc8[5]);
    acc8[6] = fmaf(w2, xv1.z, acc8[6]); acc8[7] = fmaf(w2, xv1.w, acc8[7]);
    div += w2;
    float inv = 1.f / div;
    float r8[8];
    #pragma unroll
    for (int j = 0; j < 8; j++) r8[j] = eluf(acc8[j] * inv);
    if (pair == 0) {
        uint4 st;
        st.x = h2u(__floats2half2_rn(r8[0], r8[1]));
        st.y = h2u(__floats2half2_rn(r8[2], r8[3]));
        st.z = h2u(__floats2half2_rn(r8[4], r8[5]));
        st.w = h2u(__floats2half2_rn(r8[6], r8[7]));
        uint4* mrow = reinterpret_cast<uint4*>(&g_h16a[((size_t)nxt * NA + n) * 32]);
        mrow[sub8] = st;
    }
    const float* va = &a2pa_nx[sub8 * 8];
    float4 va0 = *(const float4*)va, va1 = *(const float4*)(va + 4);
    float p = r8[0] * va0.x + r8[1] * va0.y + r8[2] * va0.z + r8[3] * va0.w
            + r8[4] * va1.x + r8[5] * va1.y + r8[6] * va1.z + r8[7] * va1.w;
    p = wred8(p);
    if ((lane & 15) == 0) g_h1pa[(size_t)h1nxt * NA + n] = p;
}

// P-side aggregation for one hop
__device__ __forceinline__ void aggP_body(int warp, int lane, int curA, int curP, int nxt,
                                          int h1cur, int h1nxt, int hop,
                                          const float* __restrict__ a2ap_nx,
                                          const float* __restrict__ a2pp_nx) {
    int sub8 = lane & 7, pair = (lane >> 3) & 1, half = lane >> 4;
    int n = warp * 2 + half;
    const uint4* __restrict__ hA4 = reinterpret_cast<const uint4*>(bufA16(curA));
    const uint4* __restrict__ hP4 = reinterpret_cast<const uint4*>(bufP16(curP));
    const float* __restrict__ h1a = g_h1pa + (size_t)h1cur * NA;
    const float* __restrict__ h1p = g_h1pp + (size_t)h1cur * NP;
    float x1a = g_x1pa[hop * NP + n];
    float x1p = g_x1pp[hop * NP + n];
    float acc1[8] = {0.f, 0.f, 0.f, 0.f, 0.f, 0.f, 0.f, 0.f};
    float acc2[8] = {0.f, 0.f, 0.f, 0.f, 0.f, 0.f, 0.f, 0.f};
    float div1 = 0.f, div2 = 0.f;
    relation_accum8(g_rp_pa, g_ts_pa, hA4, h1a, x1a, n, sub8, pair, acc1, div1);
    relation_accum8(g_rp_pp, g_ts_pp, hP4, h1p, x1p, n, sub8, pair, acc2, div2);
    combine8(acc1, div1);
    combine8(acc2, div2);
    const float* xr = &g_xp[(size_t)n * 64 + sub8 * 8];
    float4 xv0 = *(const float4*)xr;
    float4 xv1 = *(const float4*)(xr + 4);
    float w2a = lrelu_exp(x1a + g_x2pa[hop * NP + n]);
    float w2p = lrelu_exp(x1p + g_x2pp[hop * NP + n]);
    acc1[0] = fmaf(w2a, xv0.x, acc1[0]); acc1[1] = fmaf(w2a, xv0.y, acc1[1]);
    acc1[2] = fmaf(w2a, xv0.z, acc1[2]); acc1[3] = fmaf(w2a, xv0.w, acc1[3]);
    acc1[4] = fmaf(w2a, xv1.x, acc1[4]); acc1[5] = fmaf(w2a, xv1.y, acc1[5]);
    acc1[6] = fmaf(w2a, xv1.z, acc1[6]); acc1[7] = fmaf(w2a, xv1.w, acc1[7]);
    div1 += w2a;
    acc2[0] = fmaf(w2p, xv0.x, acc2[0]); acc2[1] = fmaf(w2p, xv0.y, acc2[1]);
    acc2[2] = fmaf(w2p, xv0.z, acc2[2]); acc2[3] = fmaf(w2p, xv0.w, acc2[3]);
    acc2[4] = fmaf(w2p, xv1.x, acc2[4]); acc2[5] = fmaf(w2p, xv1.y, acc2[5]);
    acc2[6] = fmaf(w2p, xv1.z, acc2[6]); acc2[7] = fmaf(w2p, xv1.w, acc2[7]);
    div2 += w2p;
    float i1 = 1.f / div1, i2 = 1.f / div2;
    float r8[8];
    #pragma unroll
    for (int j = 0; j < 8; j++) r8[j] = eluf(0.5f * (acc1[j] * i1 + acc2[j] * i2));
    if (pair == 0) {
        uint4 st;
        st.x = h2u(__floats2half2_rn(r8[0], r8[1]));
        st.y = h2u(__floats2half2_rn(r8[2], r8[3]));
        st.z = h2u(__floats2half2_rn(r8[4], r8[5]));
        st.w = h2u(__floats2half2_rn(r8[6], r8[7]));
        uint4* mrow = reinterpret_cast<uint4*>(&g_h16p[((size_t)nxt * NP + n) * 32]);
        mrow[sub8] = st;
    }
    const float* va = &a2ap_nx[sub8 * 8];
    const float* vp = &a2pp_nx[sub8 * 8];
    float4 va0 = *(const float4*)va, va1 = *(const float4*)(va + 4);
    float4 vp0 = *(const float4*)vp, vp1 = *(const float4*)(vp + 4);
    float p1 = r8[0] * va0.x + r8[1] * va0.y + r8[2] * va0.z + r8[3] * va0.w
             + r8[4] * va1.x + r8[5] * va1.y + r8[6] * va1.z + r8[7] * va1.w;
    float p2 = r8[0] * vp0.x + r8[1] * vp0.y + r8[2] * vp0.z + r8[3] * vp0.w
             + r8[4] * vp1.x + r8[5] * vp1.y + r8[6] * vp1.z + r8[7] * vp1.w;
    p1 = wred8(p1);
    p2 = wred8(p2);
    if ((lane & 15) == 0) {
        g_h1ap[(size_t)h1nxt * NP + n] = p1;
        g_h1pp[(size_t)h1nxt * NP + n] = p2;
    }
}

// hop0 split kernels
__global__ void aggA_hop_kernel(int curP, int nxt, int h1cur, int h1nxt, int hop,
                                const float* __restrict__ a2pa_nx) {
    int warp = (blockIdx.x * blockDim.x + threadIdx.x) >> 5;
    aggA_body(warp, threadIdx.x & 31, curP, nxt, h1cur, h1nxt, hop, a2pa_nx);
}
__global__ void aggP_hop_kernel(int curA, int curP, int nxt, int h1cur, int h1nxt, int hop,
                                const float* __restrict__ a2ap_nx,
                                const float* __restrict__ a2pp_nx) {
    int warp = (blockIdx.x * blockDim.x + threadIdx.x) >> 5;
    aggP_body(warp, threadIdx.x & 31, curA, curP, nxt, h1cur, h1nxt, hop, a2ap_nx, a2pp_nx);
}

// merged A+P for hop 1
__global__ void agg_kernel(int curA, int curP, int nxt, int h1cur, int h1nxt, int hop,
                           const float* __restrict__ a2pa_nx,
                           const float* __restrict__ a2ap_nx,
                           const float* __restrict__ a2pp_nx) {
    if (blockIdx.x < BA_BLOCKS) {
        int warp = (blockIdx.x * blockDim.x + threadIdx.x) >> 5;
        aggA_body(warp, threadIdx.x & 31, curP, nxt, h1cur, h1nxt, hop, a2pa_nx);
    } else {
        int warp = ((blockIdx.x - BA_BLOCKS) * blockDim.x + threadIdx.x) >> 5;
        aggP_body(warp, threadIdx.x & 31, curA, curP, nxt, h1cur, h1nxt, hop, a2ap_nx, a2pp_nx);
    }
}

// last hop: A-side aggregation only, with fc2 fused
__global__ void aggA_fc2_kernel(int curP, int h1cur,
                                const float* __restrict__ W,
                                const float* __restrict__ bias,
                                float* __restrict__ out) {
    __shared__ __align__(16) float wt[16 * 68];
    __shared__ __align__(16) float rs[8][2][64];
    int tid = threadIdx.x;
    for (int idx = tid; idx < 1024; idx += 256) {
        int k = idx >> 4, j = idx & 15;
        wt[j * 68 + k] = W[idx];
    }
    __syncthreads();

    int lane = tid & 31, sub8 = lane & 7, pair = (lane >> 3) & 1, half = lane >> 4;
    int w = tid >> 5;
    int warp = (blockIdx.x * blockDim.x + tid) >> 5;
    int n = warp * 2 + half;

    const uint4* __restrict__ h4 = reinterpret_cast<const uint4*>(bufP16(curP));
    const float* __restrict__ h1 = g_h1ap + (size_t)h1cur * NP;
    float x1 = g_x1ap[2 * NA + n];
    float acc8[8] = {0.f, 0.f, 0.f, 0.f, 0.f, 0.f, 0.f, 0.f};
    float div = 0.f;
    relation_accum8(g_rp_ap, g_ts_ap, h4, h1, x1, n, sub8, pair, acc8, div);
    combine8(acc8, div);
    float w2 = lrelu_exp(x1 + g_x2ap[2 * NA + n]);
    const float* xr = &g_xa[(size_t)n * 64 + sub8 * 8];
    float4 xv0 = *(const float4*)xr;
    float4 xv1 = *(const float4*)(xr + 4);
    acc8[0] = fmaf(w2, xv0.x, acc8[0]); acc8[1] = fmaf(w2, xv0.y, acc8[1]);
    acc8[2] = fmaf(w2, xv0.z, acc8[2]); acc8[3] = fmaf(w2, xv0.w, acc8[3]);
    acc8[4] = fmaf(w2, xv1.x, acc8[4]); acc8[5] = fmaf(w2, xv1.y, acc8[5]);
    acc8[6] = fmaf(w2, xv1.z, acc8[6]); acc8[7] = fmaf(w2, xv1.w, acc8[7]);
    div += w2;
    float inv = 1.f / div;
    float r8[8];
    #pragma unroll
    for (int j = 0; j < 8; j++) r8[j] = eluf(acc8[j] * inv);

    if (pair == 0) {
        float4 s0 = {r8[0], r8[1], r8[2], r8[3]};
        float4 s1 = {r8[4], r8[5], r8[6], r8[7]};
        *reinterpret_cast<float4*>(&rs[w][half][sub8 * 8]) = s0;
        *reinterpret_cast<float4*>(&rs[w][half][sub8 * 8 + 4]) = s1;
    }
    __syncwarp();
    int sub = lane & 15;
    float o = bias[sub];
    #pragma unroll
    for (int k4 = 0; k4 < 16; k4++) {
        float4 rv = *reinterpret_cast<const float4*>(&rs[w][half][k4 * 4]);
        float4 wv = *reinterpret_cast<const float4*>(&wt[sub * 68 + k4 * 4]);
        o += rv.x * wv.x + rv.y * wv.y + rv.z * wv.z + rv.w * wv.w;
    }
    out[(size_t)n * 16 + sub] = o;
}

// ---------------- launch ----------------
extern "C" void kernel_launch(void* const* d_in, const int* in_sizes, int n_in,
                              void* d_out, int out_size) {
    const float* x_a   = (const float*)d_in[0];
    const float* x_p   = (const float*)d_in[1];
    const int* ap_s    = (const int*)d_in[2];
    const int* ap_t    = (const int*)d_in[3];
    const int* pa_s    = (const int*)d_in[4];
    const int* pa_t    = (const int*)d_in[5];
    const int* pp_s    = (const int*)d_in[6];
    const int* pp_t    = (const int*)d_in[7];
    const float* fc1aw = (const float*)d_in[8];
    const float* fc1ab = (const float*)d_in[9];
    const float* fc1pw = (const float*)d_in[10];
    const float* fc1pb = (const float*)d_in[11];
    const float* fc2w  = (const float*)d_in[12];
    const float* fc2b  = (const float*)d_in[13];
    const float* a1ap  = (const float*)d_in[14];
    const float* a2ap  = (const float*)d_in[15];
    const float* a1pa  = (const float*)d_in[16];
    const float* a2pa  = (const float*)d_in[17];
    const float* a1pp  = (const float*)d_in[18];
    const float* a2pp  = (const float*)d_in[19];
    float* out = (float*)d_out;

    static cudaStream_t s2 = nullptr;
    static cudaEvent_t evF = nullptr, evJ = nullptr, evAp = nullptr, evA0 = nullptr;
    if (s2 == nullptr) {
        cudaStreamCreateWithFlags(&s2, cudaStreamNonBlocking);
        cudaEventCreateWithFlags(&evF, cudaEventDisableTiming);
        cudaEventCreateWithFlags(&evJ, cudaEventDisableTiming);
        cudaEventCreateWithFlags(&evAp, cudaEventDisableTiming);
        cudaEventCreateWithFlags(&evA0, cudaEventDisableTiming);
    }

    // ---- fork: projection chain on s2, CSR chain on the main stream ----
    cudaEventRecord(evF, 0);
    cudaStreamWaitEvent(s2, evF, 0);

    proj_mma<<<GEMM_A_BLOCKS + GEMM_P_BLOCKS, 256, 0, s2>>>(x_a, fc1aw, fc1ab, x_p, fc1pw, fc1pb);
    sproj0_kernel<<<(NA + NP) / 8, 256, 0, s2>>>(a1ap, a2ap, a1pa, a2pa, a1pp, a2pp);
    cudaEventRecord(evJ, s2);

    // CSR build (main stream)
    zero_cnt_kernel<<<977, 256>>>();
    hist_kernel<<<1024, 256>>>(ap_s, pa_s, pp_s);
    scan_passA<<<NBLK_SCAN, 256>>>();
    scan_passB<<<1, 96>>>();
    scan_passC<<<NBLK_SCAN, 256>>>();
    scatter_ap_kernel<<<500, 256>>>(ap_s, ap_t);
    cudaEventRecord(evAp, 0);
    scatter_papp_kernel<<<1000, 256>>>(pa_s, pa_t, pp_s, pp_t);

    // hop0-A on s2: needs ap-CSR (evAp) + projections (same stream)
    cudaStreamWaitEvent(s2, evAp, 0);
    aggA_hop_kernel<<<BA_BLOCKS, 256, 0, s2>>>(2, 0, 0, 1, 0, a2pa + 64);
    cudaEventRecord(evA0, s2);

    // hop0-P on main: needs pa/pp CSR (same stream) + projections (evJ)
    cudaStreamWaitEvent(0, evJ, 0);
    aggP_hop_kernel<<<BP_BLOCKS, 256>>>(2, 2, 0, 0, 1, 0, a2ap + 64, a2pp + 64);

    // hop1 (full A+P) after hop0-A joins
    cudaStreamWaitEvent(0, evA0, 0);
    agg_kernel<<<BA_BLOCKS + BP_BLOCKS, 256>>>(0, 0, 1, 1, 0, 1,
                                               a2pa + 128, a2ap + 128, a2pp + 128);
    aggA_fc2_kernel<<<BA_BLOCKS, 256>>>(1, 0, fc2w, fc2b, out);
}